// round 13
// baseline (speedup 1.0000x reference)
#include <cuda_runtime.h>
#include <cuda_bf16.h>
#include <math.h>
#include <stdint.h>

// ---------------------------------------------------------------------------
// CryptoInformer: 2-layer Informer encoder.
// GEMMs via mma.sync bf16 (HMMA) with 2-term bf16 split (hh+hl+lh).
// R11/R12/R13: GEMM retiled 128x256 CTA / 64x64 warp tiles (smem-BW bound
// fix: frag-read bytes per MMA cut 1.5x). Rest identical to R10.
// (R13 = third submit; R11/R12 hit GPU-acquisition timeouts.)
// ---------------------------------------------------------------------------

#define NB 2
#define NS 4095
#define NLQ 4096          // L = S+1
#define NFIN 32
#define ND 512
#define NH 8
#define NE 64
#define NDFF 2048
#define NU 45
#define NLAYERS 2
#define JG 5              // queries per attention block (45 = 5*9)
#define QKVS 1536         // row stride of fused qkv buffer

// ------------------------- scratch (device globals) ------------------------
__device__ __align__(16) float g_h  [NB*NLQ*ND];
__device__ __align__(16) float g_qkv[NB*NLQ*QKVS];   // [row][q|k|v]
__device__ __align__(16) float g_tmp[NB*NLQ*ND];
__device__ float g_M  [NB*NH*NLQ];
__device__ float g_vmean[NB*NH*NE];
__device__ int   g_idx[NLQ*NU];
__device__ int   g_top[NB*NH*NU];
// bf16 split buffers (activations)
__device__ __align__(16) __nv_bfloat16 g_hhi[NB*NLQ*ND];
__device__ __align__(16) __nv_bfloat16 g_hlo[NB*NLQ*ND];
__device__ __align__(16) __nv_bfloat16 g_xhi[NB*NLQ*NDFF];   // ctx split, then y1 split
__device__ __align__(16) __nv_bfloat16 g_xlo[NB*NLQ*NDFF];
// bf16 split buffers (weights, pre-split once per call)
__device__ __align__(16) __nv_bfloat16 g_wqkv_hi[NLAYERS*QKVS*ND];
__device__ __align__(16) __nv_bfloat16 g_wqkv_lo[NLAYERS*QKVS*ND];
__device__ __align__(16) __nv_bfloat16 g_wo_hi[NLAYERS*ND*ND];
__device__ __align__(16) __nv_bfloat16 g_wo_lo[NLAYERS*ND*ND];
__device__ __align__(16) __nv_bfloat16 g_w1_hi[NLAYERS*NDFF*ND];
__device__ __align__(16) __nv_bfloat16 g_w1_lo[NLAYERS*NDFF*ND];
__device__ __align__(16) __nv_bfloat16 g_w2_hi[NLAYERS*ND*NDFF];
__device__ __align__(16) __nv_bfloat16 g_w2_lo[NLAYERS*ND*NDFF];
__device__ float g_bqkv[NLAYERS*QKVS];

__device__ __forceinline__ void split_write(__nv_bfloat16* hi, __nv_bfloat16* lo,
                                            size_t off, float v) {
    __nv_bfloat16 h = __float2bfloat16(v);
    hi[off] = h;
    lo[off] = __float2bfloat16(v - __bfloat162float(h));
}

// ------------------------------ threefry2x32 --------------------------------
__host__ __device__ __forceinline__ unsigned tf_rotl(unsigned x, int d) {
    return (x << d) | (x >> (32 - d));
}
__host__ __device__ inline void threefry2x32(unsigned k0, unsigned k1,
                                             unsigned x0, unsigned x1,
                                             unsigned &o0, unsigned &o1) {
    unsigned ks2 = k0 ^ k1 ^ 0x1BD11BDAu;
    unsigned v0 = x0 + k0;
    unsigned v1 = x1 + k1;
#define TF_R(r) { v0 += v1; v1 = tf_rotl(v1, r); v1 ^= v0; }
    TF_R(13) TF_R(15) TF_R(26) TF_R(6)
    v0 += k1;  v1 += ks2 + 1u;
    TF_R(17) TF_R(29) TF_R(16) TF_R(24)
    v0 += ks2; v1 += k0 + 2u;
    TF_R(13) TF_R(15) TF_R(26) TF_R(6)
    v0 += k0;  v1 += k1 + 3u;
    TF_R(17) TF_R(29) TF_R(16) TF_R(24)
    v0 += k1;  v1 += ks2 + 4u;
    TF_R(13) TF_R(15) TF_R(26) TF_R(6)
    v0 += ks2; v1 += k0 + 5u;
#undef TF_R
    o0 = v0; o1 = v1;
}

__global__ void rng_idx_kernel(unsigned k2a, unsigned k2b) {
    int j = blockIdx.x * blockDim.x + threadIdx.x;
    if (j >= NLQ * NU) return;
    unsigned w0, w1;
    threefry2x32(k2a, k2b, 0u, (unsigned)j, w0, w1);
    g_idx[j] = (int)((w0 ^ w1) & 0xFFFu);
}

// ------------------- one-shot weight split (12 segments) --------------------
__global__ void presplit_kernel(const float* __restrict__ Wq,
                                const float* __restrict__ Wk,
                                const float* __restrict__ Wv,
                                const float* __restrict__ Wo,
                                const float* __restrict__ W1,
                                const float* __restrict__ W2) {
    int seg = blockIdx.y;
    int mat = seg >> 1, l = seg & 1;
    const float* src;
    __nv_bfloat16 *hi, *lo;
    size_t off; int n2;
    const int SQ = ND * ND;        // 262144
    const int SF = NDFF * ND;      // 1048576
    switch (mat) {
        case 0: src = Wq + (size_t)l * SQ; hi = g_wqkv_hi; lo = g_wqkv_lo;
                off = (size_t)l * (QKVS * ND);             n2 = SQ / 2; break;
        case 1: src = Wk + (size_t)l * SQ; hi = g_wqkv_hi; lo = g_wqkv_lo;
                off = (size_t)l * (QKVS * ND) + SQ;        n2 = SQ / 2; break;
        case 2: src = Wv + (size_t)l * SQ; hi = g_wqkv_hi; lo = g_wqkv_lo;
                off = (size_t)l * (QKVS * ND) + 2 * SQ;    n2 = SQ / 2; break;
        case 3: src = Wo + (size_t)l * SQ; hi = g_wo_hi;   lo = g_wo_lo;
                off = (size_t)l * SQ;                      n2 = SQ / 2; break;
        case 4: src = W1 + (size_t)l * SF; hi = g_w1_hi;   lo = g_w1_lo;
                off = (size_t)l * SF;                      n2 = SF / 2; break;
        default: src = W2 + (size_t)l * SF; hi = g_w2_hi;  lo = g_w2_lo;
                off = (size_t)l * SF;                      n2 = SF / 2; break;
    }
    int i = blockIdx.x * blockDim.x + threadIdx.x;
    if (i >= n2) return;
    float2 v = ((const float2*)src)[i];
    __nv_bfloat16 h0 = __float2bfloat16(v.x);
    __nv_bfloat16 h1 = __float2bfloat16(v.y);
    __nv_bfloat162 hh; hh.x = h0; hh.y = h1;
    __nv_bfloat162 ll;
    ll.x = __float2bfloat16(v.x - __bfloat162float(h0));
    ll.y = __float2bfloat16(v.y - __bfloat162float(h1));
    ((__nv_bfloat162*)(hi + off))[i] = hh;
    ((__nv_bfloat162*)(lo + off))[i] = ll;
}

__global__ void biaspack_kernel(const float* __restrict__ bq,
                                const float* __restrict__ bk,
                                const float* __restrict__ bv) {
    int t = threadIdx.x;   // 512
#pragma unroll
    for (int l = 0; l < NLAYERS; l++) {
        g_bqkv[l * QKVS + t]        = bq[l * ND + t];
        g_bqkv[l * QKVS + ND + t]   = bk[l * ND + t];
        g_bqkv[l * QKVS + 2*ND + t] = bv[l * ND + t];
    }
}

// ------------------------------ embed + pos enc -----------------------------
__global__ void embed_kernel(const float* __restrict__ x,
                             const float* __restrict__ We,
                             const float* __restrict__ be,
                             const float* __restrict__ cls) {
    int bt = blockIdx.x;                 // 0..NB*NLQ-1
    int b = bt / NLQ, t = bt % NLQ;
    __shared__ float xs[NFIN];
    if (t > 0 && threadIdx.x < NFIN)
        xs[threadIdx.x] = x[((size_t)b * NS + (t - 1)) * NFIN + threadIdx.x];
    __syncthreads();
    const float cexp = (float)(-9.210340371976184 / 512.0);  // -ln(1e4)/D
    for (int d = threadIdx.x; d < ND; d += blockDim.x) {
        float val;
        if (t == 0) {
            val = cls[d];
        } else {
            float acc = be[d];
            const float* w = We + (size_t)d * NFIN;
#pragma unroll
            for (int f = 0; f < NFIN; f++) acc += xs[f] * w[f];
            val = acc;
        }
        float freq = expf((float)(d & ~1) * cexp);
        float arg  = (float)t * freq;
        float pe   = (d & 1) ? cosf(arg) : sinf(arg);
        float o = val + pe;
        size_t off = (size_t)bt * ND + d;
        g_h[off] = o;
        split_write(g_hhi, g_hlo, off, o);
    }
}

// ----------------------------- mma.sync helpers -----------------------------
__device__ __forceinline__ uint32_t smem_u32(const void* p) {
    uint32_t a;
    asm("{ .reg .u64 t; cvta.to.shared.u64 t, %1; cvt.u32.u64 %0, t; }" : "=r"(a) : "l"(p));
    return a;
}
__device__ __forceinline__ void cp16(uint32_t dst, const void* src) {
    asm volatile("cp.async.cg.shared.global [%0], [%1], 16;" :: "r"(dst), "l"(src));
}
#define CP_COMMIT() asm volatile("cp.async.commit_group;" ::: "memory")
#define CP_WAIT(n)  asm volatile("cp.async.wait_group %0;" :: "n"(n) : "memory")

#define LDMX4(r, a) \
    asm volatile("ldmatrix.sync.aligned.m8n8.x4.shared.b16 {%0,%1,%2,%3}, [%4];" \
        : "=r"((r)[0]), "=r"((r)[1]), "=r"((r)[2]), "=r"((r)[3]) : "r"(a))

#define MMA16816(c, a, b0, b1) \
    asm volatile("mma.sync.aligned.m16n8k16.row.col.f32.bf16.bf16.f32 " \
        "{%0,%1,%2,%3}, {%4,%5,%6,%7}, {%8,%9}, {%0,%1,%2,%3};" \
        : "+f"((c)[0]), "+f"((c)[1]), "+f"((c)[2]), "+f"((c)[3]) \
        : "r"((a)[0]), "r"((a)[1]), "r"((a)[2]), "r"((a)[3]), "r"(b0), "r"(b1))

// ----------------------- bf16-split HMMA GEMM -------------------------------
// out = (Ah+Al)[M,K] @ (Bh+Bl)[N,K]^T + bias[N]  (drop Al*Bl), opt relu.
// CTA tile 128(M) x 256(N), 256 threads = 8 warps (2x4), warp tile 64x64.
// K-chunk 32, 2-stage cp.async, 1 barrier/chunk. Row stride 80B (16B-aligned
// for ldmatrix; 80/16=5 odd -> conflict-free).
#define SROWB 80
#define A_TILE_B (128 * SROWB)        // 10240
#define B_TILE_B (256 * SROWB)        // 20480
#define OFF_AH 0
#define OFF_AL A_TILE_B               // 10240
#define OFF_BH (2 * A_TILE_B)         // 20480
#define OFF_BL (2 * A_TILE_B + B_TILE_B) // 40960
#define STAGE_B (2 * A_TILE_B + 2 * B_TILE_B) // 61440
#define GEMM_SMEM (2 * STAGE_B)       // 122880
__global__ __launch_bounds__(256, 1)
void gemm_mma_kernel(const __nv_bfloat16* __restrict__ Ah,
                     const __nv_bfloat16* __restrict__ Al,
                     const __nv_bfloat16* __restrict__ Bh,
                     const __nv_bfloat16* __restrict__ Bl,
                     const float* __restrict__ bias, float* __restrict__ C,
                     __nv_bfloat16* __restrict__ Chi, __nv_bfloat16* __restrict__ Clo,
                     int Ndim, int Kdim, int relu, int mode) {
    extern __shared__ char smem[];
    uint32_t sb = smem_u32(smem);
    int tid = threadIdx.x, lane = tid & 31, w = tid >> 5;
    int wm = w & 1, wn = w >> 1;                 // 2 x 4 warp grid, 64x64 tiles
    int bm = blockIdx.y * 128, bn = blockIdx.x * 256;

    float acc[4][8][4];
#pragma unroll
    for (int i = 0; i < 4; i++)
#pragma unroll
        for (int j = 0; j < 8; j++)
#pragma unroll
            for (int r = 0; r < 4; r++) acc[i][j][r] = 0.f;

    const int nch = Kdim >> 5;

#define ISSUE(kc, soff) do {                                                   \
        _Pragma("unroll")                                                      \
        for (int j = 0; j < 2; j++) {            /* A: 128 rows x 4 segs */    \
            int id = tid + j * 256;                                            \
            int row = id >> 2, cc = id & 3;                                    \
            uint32_t dst = sb + (soff) + (uint32_t)(row * SROWB + cc * 16);    \
            size_t ga = (size_t)(bm + row) * Kdim + (kc) + cc * 8;             \
            cp16(dst + OFF_AH, Ah + ga);                                       \
            cp16(dst + OFF_AL, Al + ga);                                       \
        }                                                                      \
        _Pragma("unroll")                                                      \
        for (int j = 0; j < 4; j++) {            /* B: 256 rows x 4 segs */    \
            int id = tid + j * 256;                                            \
            int row = id >> 2, cc = id & 3;                                    \
            uint32_t dst = sb + (soff) + (uint32_t)(row * SROWB + cc * 16);    \
            size_t gb = (size_t)(bn + row) * Kdim + (kc) + cc * 8;             \
            cp16(dst + OFF_BH, Bh + gb);                                       \
            cp16(dst + OFF_BL, Bl + gb);                                       \
        }                                                                      \
        CP_COMMIT();                                                           \
    } while (0)

    ISSUE(0, 0);

    for (int c = 0; c < nch; c++) {
        CP_WAIT(0);
        __syncthreads();
        // prefetch next chunk into the other buffer (readers of it passed bar)
        if (c + 1 < nch)
            ISSUE((c + 1) << 5, (uint32_t)((c + 1) & 1) * STAGE_B);
        uint32_t soff = (uint32_t)(c & 1) * STAGE_B;

#pragma unroll
        for (int ks = 0; ks < 32; ks += 16) {
            uint32_t colb = (uint32_t)((ks + ((lane >> 4) << 3)) * 2);
            uint32_t ah[4][4], al[4][4];
#pragma unroll
            for (int mt = 0; mt < 4; mt++) {
                uint32_t ad = sb + soff + OFF_AH
                            + (uint32_t)((wm * 64 + mt * 16 + (lane & 15)) * SROWB) + colb;
                LDMX4(ah[mt], ad);
                LDMX4(al[mt], ad + A_TILE_B);
            }
            // B frags in two halves of 2 nt16-groups to limit live registers
#pragma unroll
            for (int half = 0; half < 2; half++) {
                uint32_t bh[2][4], bl[2][4];
#pragma unroll
                for (int p = 0; p < 2; p++) {
                    int nt16 = half * 2 + p;
                    uint32_t bd = sb + soff + OFF_BH
                                + (uint32_t)((wn * 64 + nt16 * 16 + (lane & 15)) * SROWB)
                                + colb;
                    LDMX4(bh[p], bd);
                    LDMX4(bl[p], bd + B_TILE_B);
                }
#pragma unroll
                for (int mt = 0; mt < 4; mt++)
#pragma unroll
                    for (int p = 0; p < 2; p++)
#pragma unroll
                        for (int s = 0; s < 2; s++) {
                            int nt = (half * 2 + p) * 2 + s;
                            MMA16816(acc[mt][nt], ah[mt], bh[p][s], bh[p][s + 2]);
                            MMA16816(acc[mt][nt], ah[mt], bl[p][s], bl[p][s + 2]);
                            MMA16816(acc[mt][nt], al[mt], bh[p][s], bh[p][s + 2]);
                        }
            }
        }
    }
#undef ISSUE

    // epilogue
#pragma unroll
    for (int mt = 0; mt < 4; mt++) {
        int m0 = bm + wm * 64 + mt * 16 + (lane >> 2);
#pragma unroll
        for (int nt = 0; nt < 8; nt++) {
            int n0 = bn + wn * 64 + nt * 8 + (lane & 3) * 2;
            float b0 = bias[n0], b1 = bias[n0 + 1];
            float v0 = acc[mt][nt][0] + b0, v1 = acc[mt][nt][1] + b1;
            float v2 = acc[mt][nt][2] + b0, v3 = acc[mt][nt][3] + b1;
            if (relu) {
                v0 = fmaxf(v0, 0.f); v1 = fmaxf(v1, 0.f);
                v2 = fmaxf(v2, 0.f); v3 = fmaxf(v3, 0.f);
            }
            if (mode == 0) {
                *(float2*)(C + (size_t)m0 * Ndim + n0)       = make_float2(v0, v1);
                *(float2*)(C + (size_t)(m0 + 8) * Ndim + n0) = make_float2(v2, v3);
            } else {
                size_t o0 = (size_t)m0 * Ndim + n0;
                size_t o1 = (size_t)(m0 + 8) * Ndim + n0;
                __nv_bfloat16 h0 = __float2bfloat16(v0), h1 = __float2bfloat16(v1);
                __nv_bfloat16 h2 = __float2bfloat16(v2), h3 = __float2bfloat16(v3);
                __nv_bfloat162 p0; p0.x = h0; p0.y = h1;
                __nv_bfloat162 p1; p1.x = h2; p1.y = h3;
                *(__nv_bfloat162*)(Chi + o0) = p0;
                *(__nv_bfloat162*)(Chi + o1) = p1;
                __nv_bfloat162 q0, q1;
                q0.x = __float2bfloat16(v0 - __bfloat162float(h0));
                q0.y = __float2bfloat16(v1 - __bfloat162float(h1));
                q1.x = __float2bfloat16(v2 - __bfloat162float(h2));
                q1.y = __float2bfloat16(v3 - __bfloat162float(h3));
                *(__nv_bfloat162*)(Clo + o0) = q0;
                *(__nv_bfloat162*)(Clo + o1) = q1;
            }
        }
    }
}

// -------------------- sparse QK sampling -> M measure -----------------------
__global__ void qks_m_kernel() {
    int gw = (blockIdx.x * blockDim.x + threadIdx.x) >> 5;
    int lane = threadIdx.x & 31;
    if (gw >= NB * NH * NLQ) return;
    int l  = gw % NLQ;
    int bh = gw / NLQ;
    int h  = bh % NH, b = bh / NH;
    const float* qrow = g_qkv + ((size_t)(b * NLQ + l)) * QKVS + h * NE;
    float2 qv = *(const float2*)(qrow + lane * 2);
    const int* idxp = g_idx + l * NU;
    const float* kbase = g_qkv + (size_t)b * NLQ * QKVS + ND + h * NE + lane * 2;
    float mx = -INFINITY, sm = 0.f;
#pragma unroll 1
    for (int j0 = 0; j0 < NU; j0 += 5) {
        int ki[5];
#pragma unroll
        for (int u = 0; u < 5; u++) ki[u] = idxp[j0 + u];
        float2 kv[5];
#pragma unroll
        for (int u = 0; u < 5; u++)
            kv[u] = *(const float2*)(kbase + (size_t)ki[u] * QKVS);
        float r[5];
#pragma unroll
        for (int u = 0; u < 5; u++) {
            float p = qv.x * kv[u].x + qv.y * kv[u].y;
#pragma unroll
            for (int o = 16; o > 0; o >>= 1)
                p += __shfl_xor_sync(0xffffffffu, p, o);
            r[u] = p;
        }
#pragma unroll
        for (int u = 0; u < 5; u++) {   // in-order accumulate (exact)
            mx = fmaxf(mx, r[u]);
            sm += r[u];
        }
    }
    if (lane == 0) g_M[gw] = mx - sm * (1.0f / (float)NLQ);
}

// ------------------------- top-k (k=45) per (b,h) ---------------------------
__global__ void topk_kernel() {
    int bh = blockIdx.x;
    __shared__ float sv[NLQ];
    __shared__ float rv[256];
    __shared__ int   ri[256];
    const float* m = g_M + (size_t)bh * NLQ;
    for (int i = threadIdx.x; i < NLQ; i += blockDim.x) sv[i] = m[i];
    __syncthreads();
    for (int it = 0; it < NU; it++) {
        float bv = -INFINITY; int bi = 0x7fffffff;
        for (int i = threadIdx.x; i < NLQ; i += blockDim.x) {
            float vv = sv[i];
            if (vv > bv) { bv = vv; bi = i; }
        }
        rv[threadIdx.x] = bv; ri[threadIdx.x] = bi;
        __syncthreads();
        for (int s = 128; s > 0; s >>= 1) {
            if (threadIdx.x < s) {
                float ov = rv[threadIdx.x + s]; int oi = ri[threadIdx.x + s];
                if (ov > rv[threadIdx.x] ||
                    (ov == rv[threadIdx.x] && oi < ri[threadIdx.x])) {
                    rv[threadIdx.x] = ov; ri[threadIdx.x] = oi;
                }
            }
            __syncthreads();
        }
        if (threadIdx.x == 0) {
            g_top[bh * NU + it] = ri[0];
            sv[ri[0]] = -INFINITY;
        }
        __syncthreads();
    }
}

// ------------------------------ v mean per (b,h) ----------------------------
__global__ void vmean_kernel() {
    int bh = blockIdx.x; int b = bh / NH, h = bh % NH;
    int e = threadIdx.x & 63, part = threadIdx.x >> 6;
    float acc = 0.f;
    for (int l = part; l < NLQ; l += 4)
        acc += g_qkv[((size_t)(b * NLQ + l)) * QKVS + 2*ND + h * NE + e];
    __shared__ float sp[4][64];
    sp[part][e] = acc;
    __syncthreads();
    if (part == 0)
        g_vmean[bh * NE + e] =
            (sp[0][e] + sp[1][e] + sp[2][e] + sp[3][e]) * (1.0f / (float)NLQ);
}

// ctx default = vmean broadcast, written as bf16 hi/lo split
__global__ void ctx_init_kernel() {
    size_t i = (size_t)blockIdx.x * blockDim.x + threadIdx.x;
    if (i >= (size_t)NB * NLQ * ND) return;
    int d = (int)(i % ND);
    int b = (int)(i / ((size_t)NLQ * ND));
    float vv = g_vmean[(b * NH + (d >> 6)) * NE + (d & 63)];
    split_write(g_xhi, g_xlo, i, vv);
}

// ---- flash-style attention for top queries: block = (b,h, group of 5) -----
#define ATTN_SMEM (128*64*4*2 + JG*64*4 + JG*128*4 + 4*JG*4 + 64)
__global__ __launch_bounds__(320)
void attn_fused_kernel() {
    extern __shared__ char asm_raw[];
    float* ks   = (float*)asm_raw;                  // [128][64]
    float* vs   = ks + 128 * 64;                    // [128][64]
    float* qs   = vs + 128 * 64;                    // [JG][64]
    float* sc   = qs + JG * 64;                     // [JG][128]
    float* jmax = sc + JG * 128;                    // [JG]
    float* jsum = jmax + JG;
    float* jfac = jsum + JG;
    int*   tpos = (int*)(jfac + JG);                // [JG]

    int grp = blockIdx.x % 9;
    int bh  = blockIdx.x / 9;
    int h = bh % NH, b = bh / NH;
    int tid = threadIdx.x;
    int j = tid >> 6;          // 0..4
    int e = tid & 63;

    if (tid < JG) {
        tpos[tid] = g_top[bh * NU + grp * JG + tid];
        jmax[tid] = -INFINITY;
        jsum[tid] = 0.f;
    }
    __syncthreads();
    qs[j * 64 + e] = g_qkv[((size_t)(b * NLQ + tpos[j])) * QKVS + h * NE + e];
    __syncthreads();

    float cacc = 0.f;
    const size_t kvbase = (size_t)b * NLQ * QKVS + h * NE;

#pragma unroll 1
    for (int t = 0; t < NLQ / 128; t++) {
        int l0 = t * 128;
        for (int i = tid; i < 2048; i += 320) {
            int r = i >> 4, c4 = i & 15;
            size_t go = kvbase + (size_t)(l0 + r) * QKVS + c4 * 4;
            ((float4*)ks)[r * 16 + c4] = *(const float4*)(g_qkv + go + ND);
            ((float4*)vs)[r * 16 + c4] = *(const float4*)(g_qkv + go + 2*ND);
        }
        __syncthreads();
        for (int idx = tid; idx < JG * 128; idx += 320) {
            int jj = idx >> 7, ll = idx & 127;
            const float4* kr = (const float4*)(ks + ll * 64);
            const float4* qr = (const float4*)(qs + jj * 64);
            float s0 = 0.f, s1 = 0.f, s2 = 0.f, s3 = 0.f;
#pragma unroll
            for (int e4 = 0; e4 < 16; e4 += 4) {
                float4 a0 = kr[e4],     q0 = qr[e4];
                float4 a1 = kr[e4 + 1], q1 = qr[e4 + 1];
                float4 a2 = kr[e4 + 2], q2 = qr[e4 + 2];
                float4 a3 = kr[e4 + 3], q3 = qr[e4 + 3];
                s0 += a0.x * q0.x + a0.y * q0.y + a0.z * q0.z + a0.w * q0.w;
                s1 += a1.x * q1.x + a1.y * q1.y + a1.z * q1.z + a1.w * q1.w;
                s2 += a2.x * q2.x + a2.y * q2.y + a2.z * q2.z + a2.w * q2.w;
                s3 += a3.x * q3.x + a3.y * q3.y + a3.z * q3.z + a3.w * q3.w;
            }
            sc[jj * 128 + ll] = ((s0 + s1) + (s2 + s3)) * 0.125f;
        }
        __syncthreads();
        int w = tid >> 5, lane = tid & 31;
        if (w < JG) {
            float m = fmaxf(fmaxf(sc[w * 128 + lane], sc[w * 128 + lane + 32]),
                            fmaxf(sc[w * 128 + lane + 64], sc[w * 128 + lane + 96]));
#pragma unroll
            for (int o = 16; o > 0; o >>= 1)
                m = fmaxf(m, __shfl_xor_sync(0xffffffffu, m, o));
            if (lane == 0) {
                float old = jmax[w];
                float nm = fmaxf(old, m);
                jfac[w] = expf(old - nm);
                jmax[w] = nm;
            }
        }
        __syncthreads();
        for (int idx = tid; idx < JG * 128; idx += 320) {
            int jj = idx >> 7;
            sc[idx] = expf(sc[idx] - jmax[jj]);
        }
        __syncthreads();
        if (w < JG) {
            float s = sc[w * 128 + lane] + sc[w * 128 + lane + 32]
                    + sc[w * 128 + lane + 64] + sc[w * 128 + lane + 96];
#pragma unroll
            for (int o = 16; o > 0; o >>= 1)
                s += __shfl_xor_sync(0xffffffffu, s, o);
            if (lane == 0) jsum[w] = jsum[w] * jfac[w] + s;
        }
        {
            float a0 = 0.f, a1 = 0.f, a2 = 0.f, a3 = 0.f;
            const float* sj = sc + j * 128;
#pragma unroll 8
            for (int l = 0; l < 128; l += 4) {
                a0 += sj[l]     * vs[(l)     * 64 + e];
                a1 += sj[l + 1] * vs[(l + 1) * 64 + e];
                a2 += sj[l + 2] * vs[(l + 2) * 64 + e];
                a3 += sj[l + 3] * vs[(l + 3) * 64 + e];
            }
            cacc = cacc * jfac[j] + ((a0 + a1) + (a2 + a3));
        }
        __syncthreads();
    }

    float u = cacc / jsum[j];
    size_t off = ((size_t)(b * NLQ + tpos[j])) * ND + h * NE + e;
    split_write(g_xhi, g_xlo, off, u);
}

// ------------------- residual add + layernorm (+ split) ---------------------
__global__ __launch_bounds__(256)
void add_ln_kernel(float* __restrict__ hbuf, const float* __restrict__ a,
                   const float* __restrict__ g, const float* __restrict__ bta) {
    size_t row = blockIdx.x;
    int t = threadIdx.x;
    float x0 = hbuf[row * ND + t]       + a[row * ND + t];
    float x1 = hbuf[row * ND + 256 + t] + a[row * ND + 256 + t];
    __shared__ float red[256];
    red[t] = x0 + x1; __syncthreads();
    for (int s = 128; s > 0; s >>= 1) {
        if (t < s) red[t] += red[t + s];
        __syncthreads();
    }
    float mean = red[0] * (1.0f / (float)ND);
    __syncthreads();
    float d0 = x0 - mean, d1 = x1 - mean;
    red[t] = d0 * d0 + d1 * d1; __syncthreads();
    for (int s = 128; s > 0; s >>= 1) {
        if (t < s) red[t] += red[t + s];
        __syncthreads();
    }
    float var = red[0] * (1.0f / (float)ND);
    float inv = 1.0f / sqrtf(var + 1e-5f);
    float o0 = d0 * inv * g[t]       + bta[t];
    float o1 = d1 * inv * g[256 + t] + bta[256 + t];
    hbuf[row * ND + t]       = o0;
    hbuf[row * ND + 256 + t] = o1;
    split_write(g_hhi, g_hlo, row * ND + t, o0);
    split_write(g_hhi, g_hlo, row * ND + 256 + t, o1);
}

// ------------------------------- final readout ------------------------------
__global__ void final_kernel(const float* __restrict__ Wf,
                             const float* __restrict__ bf, float* __restrict__ out) {
    int b = blockIdx.x;
    float acc = 0.f;
    for (int d = threadIdx.x; d < ND; d += 256)
        acc += g_h[(size_t)b * NLQ * ND + d] * Wf[d];
    __shared__ float red[256];
    red[threadIdx.x] = acc; __syncthreads();
    for (int s = 128; s > 0; s >>= 1) {
        if (threadIdx.x < s) red[threadIdx.x] += red[threadIdx.x + s];
        __syncthreads();
    }
    if (threadIdx.x == 0) out[b] = red[0] + bf[0];
}

// --------------------------------- launch -----------------------------------
extern "C" void kernel_launch(void* const* d_in, const int* in_sizes, int n_in,
                              void* d_out, int out_size) {
    (void)in_sizes; (void)n_in; (void)out_size;
    const float* x   = (const float*)d_in[0];
    const float* We  = (const float*)d_in[1];
    const float* be  = (const float*)d_in[2];
    const float* cls = (const float*)d_in[3];
    const float* Wq  = (const float*)d_in[4];
    const float* bq  = (const float*)d_in[5];
    const float* Wk  = (const float*)d_in[6];
    const float* bk  = (const float*)d_in[7];
    const float* Wv  = (const float*)d_in[8];
    const float* bv  = (const float*)d_in[9];
    const float* Wo  = (const float*)d_in[10];
    const float* bo  = (const float*)d_in[11];
    const float* g1  = (const float*)d_in[12];
    const float* b1  = (const float*)d_in[13];
    const float* g2  = (const float*)d_in[14];
    const float* b2  = (const float*)d_in[15];
    const float* W1  = (const float*)d_in[16];
    const float* bf1 = (const float*)d_in[17];
    const float* W2  = (const float*)d_in[18];
    const float* bf2 = (const float*)d_in[19];
    const float* Wf  = (const float*)d_in[20];
    const float* bf  = (const float*)d_in[21];

    float *h, *qkv, *tmp, *bqkv;
    __nv_bfloat16 *hhi, *hlo, *xhi, *xlo;
    __nv_bfloat16 *wqh, *wql, *woh, *wol, *w1h, *w1l, *w2h, *w2l;
    cudaGetSymbolAddress((void**)&h,    g_h);
    cudaGetSymbolAddress((void**)&qkv,  g_qkv);
    cudaGetSymbolAddress((void**)&tmp,  g_tmp);
    cudaGetSymbolAddress((void**)&bqkv, g_bqkv);
    cudaGetSymbolAddress((void**)&hhi,  g_hhi);
    cudaGetSymbolAddress((void**)&hlo,  g_hlo);
    cudaGetSymbolAddress((void**)&xhi,  g_xhi);
    cudaGetSymbolAddress((void**)&xlo,  g_xlo);
    cudaGetSymbolAddress((void**)&wqh,  g_wqkv_hi);
    cudaGetSymbolAddress((void**)&wql,  g_wqkv_lo);
    cudaGetSymbolAddress((void**)&woh,  g_wo_hi);
    cudaGetSymbolAddress((void**)&wol,  g_wo_lo);
    cudaGetSymbolAddress((void**)&w1h,  g_w1_hi);
    cudaGetSymbolAddress((void**)&w1l,  g_w1_lo);
    cudaGetSymbolAddress((void**)&w2h,  g_w2_hi);
    cudaGetSymbolAddress((void**)&w2l,  g_w2_lo);

    cudaFuncSetAttribute(gemm_mma_kernel,
                         cudaFuncAttributeMaxDynamicSharedMemorySize, GEMM_SMEM);
    cudaFuncSetAttribute(attn_fused_kernel,
                         cudaFuncAttributeMaxDynamicSharedMemorySize, ATTN_SMEM);

    const int Mrows = NB * NLQ;               // 8192

#define GEMM_F32(ah, al, bh, bl, bias, Cout, N, K, relu) \
    gemm_mma_kernel<<<dim3((N) / 256, Mrows / 128), 256, GEMM_SMEM>>>( \
        ah, al, bh, bl, bias, Cout, nullptr, nullptr, N, K, relu, 0)
#define GEMM_SPL(ah, al, bh, bl, bias, Hout, Lout, N, K, relu) \
    gemm_mma_kernel<<<dim3((N) / 256, Mrows / 128), 256, GEMM_SMEM>>>( \
        ah, al, bh, bl, bias, nullptr, Hout, Lout, N, K, relu, 1)

    presplit_kernel<<<dim3(2048, 12), 256>>>(Wq, Wk, Wv, Wo, W1, W2);
    biaspack_kernel<<<1, 512>>>(bq, bk, bv);
    embed_kernel<<<NB * NLQ, 256>>>(x, We, be, cls);

    for (int l = 0; l < NLAYERS; l++) {
        // ---- fused QKV projection (N=1536) ----
        GEMM_F32(hhi, hlo, wqh + (size_t)l * QKVS * ND, wql + (size_t)l * QKVS * ND,
                 bqkv + l * QKVS, qkv, QKVS, ND, 0);

        // ---- ProbSparse attention ----
        unsigned r0, r1;
        threefry2x32(0u, 42u, 0u, (unsigned)l, r0, r1);
        unsigned k2a, k2b;
        threefry2x32(r0, r1, 0u, 1u, k2a, k2b);
        rng_idx_kernel<<<(NLQ * NU + 255) / 256, 256>>>(k2a, k2b);
        qks_m_kernel<<<(NB * NH * NLQ * 32) / 256, 256>>>();
        topk_kernel<<<NB * NH, 256>>>();
        vmean_kernel<<<NB * NH, 256>>>();
        ctx_init_kernel<<<(NB * NLQ * ND + 255) / 256, 256>>>();
        attn_fused_kernel<<<NB * NH * 9, 320, ATTN_SMEM>>>();

        // ---- output projection + LN1 ----
        GEMM_F32(xhi, xlo, woh + (size_t)l * ND * ND, wol + (size_t)l * ND * ND,
                 bo + l * ND, tmp, ND, ND, 0);
        add_ln_kernel<<<Mrows, 256>>>(h, tmp, g1 + l * ND, b1 + l * ND);

        // ---- FFN + LN2 ----
        GEMM_SPL(hhi, hlo, w1h + (size_t)l * NDFF * ND, w1l + (size_t)l * NDFF * ND,
                 bf1 + l * NDFF, xhi, xlo, NDFF, ND, 1);
        GEMM_F32(xhi, xlo, w2h + (size_t)l * ND * NDFF, w2l + (size_t)l * ND * NDFF,
                 bf2 + l * ND, tmp, ND, NDFF, 0);
        add_ln_kernel<<<Mrows, 256>>>(h, tmp, g2 + l * ND, b2 + l * ND);
    }

    final_kernel<<<NB, 256>>>(Wf, bf, (float*)d_out);
#undef GEMM_F32
#undef GEMM_SPL
}

// round 16
// speedup vs baseline: 1.0946x; 1.0946x over previous
#include <cuda_runtime.h>
#include <cuda_bf16.h>
#include <math.h>
#include <stdint.h>

// ---------------------------------------------------------------------------
// CryptoInformer: 2-layer Informer encoder.
// GEMMs via mma.sync bf16 (HMMA) with 2-term bf16 split (hh+hl+lh).
// R14/R15/R16: GEMM reverted to proven R10 tiling (128x128, 2 CTA/SM,
// regs=128; R13's 128x256 retile spilled at regs=254 and regressed). New:
// attention double-buffered cp.async tile loads; add_ln float2/bf16x2
// vectorization. (R16 = third submit; R14/R15 hit GPU-acquisition timeouts.)
// ---------------------------------------------------------------------------

#define NB 2
#define NS 4095
#define NLQ 4096          // L = S+1
#define NFIN 32
#define ND 512
#define NH 8
#define NE 64
#define NDFF 2048
#define NU 45
#define NLAYERS 2
#define JG 5              // queries per attention block (45 = 5*9)
#define QKVS 1536         // row stride of fused qkv buffer

// ------------------------- scratch (device globals) ------------------------
__device__ __align__(16) float g_h  [NB*NLQ*ND];
__device__ __align__(16) float g_qkv[NB*NLQ*QKVS];   // [row][q|k|v]
__device__ __align__(16) float g_tmp[NB*NLQ*ND];
__device__ float g_M  [NB*NH*NLQ];
__device__ float g_vmean[NB*NH*NE];
__device__ int   g_idx[NLQ*NU];
__device__ int   g_top[NB*NH*NU];
// bf16 split buffers (activations)
__device__ __align__(16) __nv_bfloat16 g_hhi[NB*NLQ*ND];
__device__ __align__(16) __nv_bfloat16 g_hlo[NB*NLQ*ND];
__device__ __align__(16) __nv_bfloat16 g_xhi[NB*NLQ*NDFF];   // ctx split, then y1 split
__device__ __align__(16) __nv_bfloat16 g_xlo[NB*NLQ*NDFF];
// bf16 split buffers (weights, pre-split once per call)
__device__ __align__(16) __nv_bfloat16 g_wqkv_hi[NLAYERS*QKVS*ND];
__device__ __align__(16) __nv_bfloat16 g_wqkv_lo[NLAYERS*QKVS*ND];
__device__ __align__(16) __nv_bfloat16 g_wo_hi[NLAYERS*ND*ND];
__device__ __align__(16) __nv_bfloat16 g_wo_lo[NLAYERS*ND*ND];
__device__ __align__(16) __nv_bfloat16 g_w1_hi[NLAYERS*NDFF*ND];
__device__ __align__(16) __nv_bfloat16 g_w1_lo[NLAYERS*NDFF*ND];
__device__ __align__(16) __nv_bfloat16 g_w2_hi[NLAYERS*ND*NDFF];
__device__ __align__(16) __nv_bfloat16 g_w2_lo[NLAYERS*ND*NDFF];
__device__ float g_bqkv[NLAYERS*QKVS];

__device__ __forceinline__ void split_write(__nv_bfloat16* hi, __nv_bfloat16* lo,
                                            size_t off, float v) {
    __nv_bfloat16 h = __float2bfloat16(v);
    hi[off] = h;
    lo[off] = __float2bfloat16(v - __bfloat162float(h));
}

// ------------------------------ threefry2x32 --------------------------------
__host__ __device__ __forceinline__ unsigned tf_rotl(unsigned x, int d) {
    return (x << d) | (x >> (32 - d));
}
__host__ __device__ inline void threefry2x32(unsigned k0, unsigned k1,
                                             unsigned x0, unsigned x1,
                                             unsigned &o0, unsigned &o1) {
    unsigned ks2 = k0 ^ k1 ^ 0x1BD11BDAu;
    unsigned v0 = x0 + k0;
    unsigned v1 = x1 + k1;
#define TF_R(r) { v0 += v1; v1 = tf_rotl(v1, r); v1 ^= v0; }
    TF_R(13) TF_R(15) TF_R(26) TF_R(6)
    v0 += k1;  v1 += ks2 + 1u;
    TF_R(17) TF_R(29) TF_R(16) TF_R(24)
    v0 += ks2; v1 += k0 + 2u;
    TF_R(13) TF_R(15) TF_R(26) TF_R(6)
    v0 += k0;  v1 += k1 + 3u;
    TF_R(17) TF_R(29) TF_R(16) TF_R(24)
    v0 += k1;  v1 += ks2 + 4u;
    TF_R(13) TF_R(15) TF_R(26) TF_R(6)
    v0 += ks2; v1 += k0 + 5u;
#undef TF_R
    o0 = v0; o1 = v1;
}

__global__ void rng_idx_kernel(unsigned k2a, unsigned k2b) {
    int j = blockIdx.x * blockDim.x + threadIdx.x;
    if (j >= NLQ * NU) return;
    unsigned w0, w1;
    threefry2x32(k2a, k2b, 0u, (unsigned)j, w0, w1);
    g_idx[j] = (int)((w0 ^ w1) & 0xFFFu);
}

// ------------------- one-shot weight split (12 segments) --------------------
__global__ void presplit_kernel(const float* __restrict__ Wq,
                                const float* __restrict__ Wk,
                                const float* __restrict__ Wv,
                                const float* __restrict__ Wo,
                                const float* __restrict__ W1,
                                const float* __restrict__ W2) {
    int seg = blockIdx.y;
    int mat = seg >> 1, l = seg & 1;
    const float* src;
    __nv_bfloat16 *hi, *lo;
    size_t off; int n2;
    const int SQ = ND * ND;        // 262144
    const int SF = NDFF * ND;      // 1048576
    switch (mat) {
        case 0: src = Wq + (size_t)l * SQ; hi = g_wqkv_hi; lo = g_wqkv_lo;
                off = (size_t)l * (QKVS * ND);             n2 = SQ / 2; break;
        case 1: src = Wk + (size_t)l * SQ; hi = g_wqkv_hi; lo = g_wqkv_lo;
                off = (size_t)l * (QKVS * ND) + SQ;        n2 = SQ / 2; break;
        case 2: src = Wv + (size_t)l * SQ; hi = g_wqkv_hi; lo = g_wqkv_lo;
                off = (size_t)l * (QKVS * ND) + 2 * SQ;    n2 = SQ / 2; break;
        case 3: src = Wo + (size_t)l * SQ; hi = g_wo_hi;   lo = g_wo_lo;
                off = (size_t)l * SQ;                      n2 = SQ / 2; break;
        case 4: src = W1 + (size_t)l * SF; hi = g_w1_hi;   lo = g_w1_lo;
                off = (size_t)l * SF;                      n2 = SF / 2; break;
        default: src = W2 + (size_t)l * SF; hi = g_w2_hi;  lo = g_w2_lo;
                off = (size_t)l * SF;                      n2 = SF / 2; break;
    }
    int i = blockIdx.x * blockDim.x + threadIdx.x;
    if (i >= n2) return;
    float2 v = ((const float2*)src)[i];
    __nv_bfloat16 h0 = __float2bfloat16(v.x);
    __nv_bfloat16 h1 = __float2bfloat16(v.y);
    __nv_bfloat162 hh; hh.x = h0; hh.y = h1;
    __nv_bfloat162 ll;
    ll.x = __float2bfloat16(v.x - __bfloat162float(h0));
    ll.y = __float2bfloat16(v.y - __bfloat162float(h1));
    ((__nv_bfloat162*)(hi + off))[i] = hh;
    ((__nv_bfloat162*)(lo + off))[i] = ll;
}

__global__ void biaspack_kernel(const float* __restrict__ bq,
                                const float* __restrict__ bk,
                                const float* __restrict__ bv) {
    int t = threadIdx.x;   // 512
#pragma unroll
    for (int l = 0; l < NLAYERS; l++) {
        g_bqkv[l * QKVS + t]        = bq[l * ND + t];
        g_bqkv[l * QKVS + ND + t]   = bk[l * ND + t];
        g_bqkv[l * QKVS + 2*ND + t] = bv[l * ND + t];
    }
}

// ------------------------------ embed + pos enc -----------------------------
__global__ void embed_kernel(const float* __restrict__ x,
                             const float* __restrict__ We,
                             const float* __restrict__ be,
                             const float* __restrict__ cls) {
    int bt = blockIdx.x;                 // 0..NB*NLQ-1
    int b = bt / NLQ, t = bt % NLQ;
    __shared__ float xs[NFIN];
    if (t > 0 && threadIdx.x < NFIN)
        xs[threadIdx.x] = x[((size_t)b * NS + (t - 1)) * NFIN + threadIdx.x];
    __syncthreads();
    const float cexp = (float)(-9.210340371976184 / 512.0);  // -ln(1e4)/D
    for (int d = threadIdx.x; d < ND; d += blockDim.x) {
        float val;
        if (t == 0) {
            val = cls[d];
        } else {
            float acc = be[d];
            const float* w = We + (size_t)d * NFIN;
#pragma unroll
            for (int f = 0; f < NFIN; f++) acc += xs[f] * w[f];
            val = acc;
        }
        float freq = expf((float)(d & ~1) * cexp);
        float arg  = (float)t * freq;
        float pe   = (d & 1) ? cosf(arg) : sinf(arg);
        float o = val + pe;
        size_t off = (size_t)bt * ND + d;
        g_h[off] = o;
        split_write(g_hhi, g_hlo, off, o);
    }
}

// ----------------------------- mma.sync helpers -----------------------------
__device__ __forceinline__ uint32_t smem_u32(const void* p) {
    uint32_t a;
    asm("{ .reg .u64 t; cvta.to.shared.u64 t, %1; cvt.u32.u64 %0, t; }" : "=r"(a) : "l"(p));
    return a;
}
__device__ __forceinline__ void cp16(uint32_t dst, const void* src) {
    asm volatile("cp.async.cg.shared.global [%0], [%1], 16;" :: "r"(dst), "l"(src));
}
#define CP_COMMIT() asm volatile("cp.async.commit_group;" ::: "memory")
#define CP_WAIT(n)  asm volatile("cp.async.wait_group %0;" :: "n"(n) : "memory")

#define LDMX4(r, a) \
    asm volatile("ldmatrix.sync.aligned.m8n8.x4.shared.b16 {%0,%1,%2,%3}, [%4];" \
        : "=r"((r)[0]), "=r"((r)[1]), "=r"((r)[2]), "=r"((r)[3]) : "r"(a))

#define MMA16816(c, a, b0, b1) \
    asm volatile("mma.sync.aligned.m16n8k16.row.col.f32.bf16.bf16.f32 " \
        "{%0,%1,%2,%3}, {%4,%5,%6,%7}, {%8,%9}, {%0,%1,%2,%3};" \
        : "+f"((c)[0]), "+f"((c)[1]), "+f"((c)[2]), "+f"((c)[3]) \
        : "r"((a)[0]), "r"((a)[1]), "r"((a)[2]), "r"((a)[3]), "r"(b0), "r"(b1))

// ----------------------- bf16-split HMMA GEMM (R10 proven) ------------------
// out = (Ah+Al)[M,K] @ (Bh+Bl)[N,K]^T + bias[N]  (drop Al*Bl), opt relu.
// 128x128 CTA, 256 threads (2x4 warps, 64x32 warp tiles), K-chunk 32,
// 2-stage cp.async, 1 barrier/chunk. Row stride 80B.
#define SROWB 80                      // bytes per smem row
#define TILE_B (128 * SROWB)          // 10240 bytes per tile
#define STAGE_B (4 * TILE_B)          // 40960: AH AL BH BL
#define GEMM_SMEM (2 * STAGE_B)       // 81920
__global__ __launch_bounds__(256, 2)
void gemm_mma_kernel(const __nv_bfloat16* __restrict__ Ah,
                     const __nv_bfloat16* __restrict__ Al,
                     const __nv_bfloat16* __restrict__ Bh,
                     const __nv_bfloat16* __restrict__ Bl,
                     const float* __restrict__ bias, float* __restrict__ C,
                     __nv_bfloat16* __restrict__ Chi, __nv_bfloat16* __restrict__ Clo,
                     int Ndim, int Kdim, int relu, int mode) {
    extern __shared__ char smem[];
    uint32_t sb = smem_u32(smem);
    int tid = threadIdx.x, lane = tid & 31, w = tid >> 5;
    int wm = w & 1, wn = w >> 1;                 // 2 x 4 warp grid
    int bm = blockIdx.y * 128, bn = blockIdx.x * 128;

    float acc[4][4][4];
#pragma unroll
    for (int i = 0; i < 4; i++)
#pragma unroll
        for (int j = 0; j < 4; j++)
#pragma unroll
            for (int r = 0; r < 4; r++) acc[i][j][r] = 0.f;

    const int nch = Kdim >> 5;

#define ISSUE(kc, soff) do {                                                   \
        _Pragma("unroll")                                                      \
        for (int j = 0; j < 2; j++) {                                          \
            int id = tid + j * 256;                                            \
            int row = id >> 2, cc = id & 3;                                    \
            uint32_t dst = sb + (soff) + (uint32_t)(row * SROWB + cc * 16);    \
            size_t ga = (size_t)(bm + row) * Kdim + (kc) + cc * 8;             \
            size_t gb = (size_t)(bn + row) * Kdim + (kc) + cc * 8;             \
            cp16(dst,              Ah + ga);                                   \
            cp16(dst + TILE_B,     Al + ga);                                   \
            cp16(dst + 2 * TILE_B, Bh + gb);                                   \
            cp16(dst + 3 * TILE_B, Bl + gb);                                   \
        }                                                                      \
        CP_COMMIT();                                                           \
    } while (0)

    ISSUE(0, 0);

    for (int c = 0; c < nch; c++) {
        CP_WAIT(0);
        __syncthreads();
        if (c + 1 < nch)
            ISSUE((c + 1) << 5, (uint32_t)((c + 1) & 1) * STAGE_B);
        uint32_t soff = (uint32_t)(c & 1) * STAGE_B;

#pragma unroll
        for (int ks = 0; ks < 32; ks += 16) {
            uint32_t colb = (uint32_t)((ks + ((lane >> 4) << 3)) * 2);
            uint32_t ah[4][4], al[4][4];
#pragma unroll
            for (int mt = 0; mt < 4; mt++) {
                uint32_t ad = sb + soff
                            + (uint32_t)((wm * 64 + mt * 16 + (lane & 15)) * SROWB) + colb;
                LDMX4(ah[mt], ad);
                LDMX4(al[mt], ad + TILE_B);
            }
            uint32_t bh[2][4], bl[2][4];
#pragma unroll
            for (int p = 0; p < 2; p++) {
                uint32_t bd = sb + soff + 2 * TILE_B
                            + (uint32_t)((wn * 32 + p * 16 + (lane & 15)) * SROWB) + colb;
                LDMX4(bh[p], bd);
                LDMX4(bl[p], bd + TILE_B);
            }
#pragma unroll
            for (int mt = 0; mt < 4; mt++)
#pragma unroll
                for (int nt = 0; nt < 4; nt++) {
                    int p = nt >> 1, s = nt & 1;
                    MMA16816(acc[mt][nt], ah[mt], bh[p][s], bh[p][s + 2]);
                    MMA16816(acc[mt][nt], ah[mt], bl[p][s], bl[p][s + 2]);
                    MMA16816(acc[mt][nt], al[mt], bh[p][s], bh[p][s + 2]);
                }
        }
    }
#undef ISSUE

    // epilogue
#pragma unroll
    for (int mt = 0; mt < 4; mt++) {
        int m0 = bm + wm * 64 + mt * 16 + (lane >> 2);
#pragma unroll
        for (int nt = 0; nt < 4; nt++) {
            int n0 = bn + wn * 32 + nt * 8 + (lane & 3) * 2;
            float b0 = bias[n0], b1 = bias[n0 + 1];
            float v0 = acc[mt][nt][0] + b0, v1 = acc[mt][nt][1] + b1;
            float v2 = acc[mt][nt][2] + b0, v3 = acc[mt][nt][3] + b1;
            if (relu) {
                v0 = fmaxf(v0, 0.f); v1 = fmaxf(v1, 0.f);
                v2 = fmaxf(v2, 0.f); v3 = fmaxf(v3, 0.f);
            }
            if (mode == 0) {
                *(float2*)(C + (size_t)m0 * Ndim + n0)       = make_float2(v0, v1);
                *(float2*)(C + (size_t)(m0 + 8) * Ndim + n0) = make_float2(v2, v3);
            } else {
                size_t o0 = (size_t)m0 * Ndim + n0;
                size_t o1 = (size_t)(m0 + 8) * Ndim + n0;
                __nv_bfloat16 h0 = __float2bfloat16(v0), h1 = __float2bfloat16(v1);
                __nv_bfloat16 h2 = __float2bfloat16(v2), h3 = __float2bfloat16(v3);
                __nv_bfloat162 p0; p0.x = h0; p0.y = h1;
                __nv_bfloat162 p1; p1.x = h2; p1.y = h3;
                *(__nv_bfloat162*)(Chi + o0) = p0;
                *(__nv_bfloat162*)(Chi + o1) = p1;
                __nv_bfloat162 q0, q1;
                q0.x = __float2bfloat16(v0 - __bfloat162float(h0));
                q0.y = __float2bfloat16(v1 - __bfloat162float(h1));
                q1.x = __float2bfloat16(v2 - __bfloat162float(h2));
                q1.y = __float2bfloat16(v3 - __bfloat162float(h3));
                *(__nv_bfloat162*)(Clo + o0) = q0;
                *(__nv_bfloat162*)(Clo + o1) = q1;
            }
        }
    }
}

// -------------------- sparse QK sampling -> M measure -----------------------
__global__ void qks_m_kernel() {
    int gw = (blockIdx.x * blockDim.x + threadIdx.x) >> 5;
    int lane = threadIdx.x & 31;
    if (gw >= NB * NH * NLQ) return;
    int l  = gw % NLQ;
    int bh = gw / NLQ;
    int h  = bh % NH, b = bh / NH;
    const float* qrow = g_qkv + ((size_t)(b * NLQ + l)) * QKVS + h * NE;
    float2 qv = *(const float2*)(qrow + lane * 2);
    const int* idxp = g_idx + l * NU;
    const float* kbase = g_qkv + (size_t)b * NLQ * QKVS + ND + h * NE + lane * 2;
    float mx = -INFINITY, sm = 0.f;
#pragma unroll 1
    for (int j0 = 0; j0 < NU; j0 += 5) {
        int ki[5];
#pragma unroll
        for (int u = 0; u < 5; u++) ki[u] = idxp[j0 + u];
        float2 kv[5];
#pragma unroll
        for (int u = 0; u < 5; u++)
            kv[u] = *(const float2*)(kbase + (size_t)ki[u] * QKVS);
        float r[5];
#pragma unroll
        for (int u = 0; u < 5; u++) {
            float p = qv.x * kv[u].x + qv.y * kv[u].y;
#pragma unroll
            for (int o = 16; o > 0; o >>= 1)
                p += __shfl_xor_sync(0xffffffffu, p, o);
            r[u] = p;
        }
#pragma unroll
        for (int u = 0; u < 5; u++) {   // in-order accumulate (exact)
            mx = fmaxf(mx, r[u]);
            sm += r[u];
        }
    }
    if (lane == 0) g_M[gw] = mx - sm * (1.0f / (float)NLQ);
}

// ------------------------- top-k (k=45) per (b,h) ---------------------------
__global__ void topk_kernel() {
    int bh = blockIdx.x;
    __shared__ float sv[NLQ];
    __shared__ float rv[256];
    __shared__ int   ri[256];
    const float* m = g_M + (size_t)bh * NLQ;
    for (int i = threadIdx.x; i < NLQ; i += blockDim.x) sv[i] = m[i];
    __syncthreads();
    for (int it = 0; it < NU; it++) {
        float bv = -INFINITY; int bi = 0x7fffffff;
        for (int i = threadIdx.x; i < NLQ; i += blockDim.x) {
            float vv = sv[i];
            if (vv > bv) { bv = vv; bi = i; }
        }
        rv[threadIdx.x] = bv; ri[threadIdx.x] = bi;
        __syncthreads();
        for (int s = 128; s > 0; s >>= 1) {
            if (threadIdx.x < s) {
                float ov = rv[threadIdx.x + s]; int oi = ri[threadIdx.x + s];
                if (ov > rv[threadIdx.x] ||
                    (ov == rv[threadIdx.x] && oi < ri[threadIdx.x])) {
                    rv[threadIdx.x] = ov; ri[threadIdx.x] = oi;
                }
            }
            __syncthreads();
        }
        if (threadIdx.x == 0) {
            g_top[bh * NU + it] = ri[0];
            sv[ri[0]] = -INFINITY;
        }
        __syncthreads();
    }
}

// ------------------------------ v mean per (b,h) ----------------------------
__global__ void vmean_kernel() {
    int bh = blockIdx.x; int b = bh / NH, h = bh % NH;
    int e = threadIdx.x & 63, part = threadIdx.x >> 6;
    float acc = 0.f;
    for (int l = part; l < NLQ; l += 4)
        acc += g_qkv[((size_t)(b * NLQ + l)) * QKVS + 2*ND + h * NE + e];
    __shared__ float sp[4][64];
    sp[part][e] = acc;
    __syncthreads();
    if (part == 0)
        g_vmean[bh * NE + e] =
            (sp[0][e] + sp[1][e] + sp[2][e] + sp[3][e]) * (1.0f / (float)NLQ);
}

// ctx default = vmean broadcast, written as bf16 hi/lo split
__global__ void ctx_init_kernel() {
    size_t i = (size_t)blockIdx.x * blockDim.x + threadIdx.x;
    if (i >= (size_t)NB * NLQ * ND) return;
    int d = (int)(i % ND);
    int b = (int)(i / ((size_t)NLQ * ND));
    float vv = g_vmean[(b * NH + (d >> 6)) * NE + (d & 63)];
    split_write(g_xhi, g_xlo, i, vv);
}

// ---- flash-style attention, double-buffered cp.async K/V tile loads --------
// block = (b,h, group of 5 top queries); 320 threads.
#define KV_STAGE_B (128 * 64 * 4)                 // 32768 bytes per tensor/stage
#define ATTN_SMEM (4 * KV_STAGE_B + JG*64*4 + JG*128*4 + 4*JG*4 + 64)
__global__ __launch_bounds__(320)
void attn_fused_kernel() {
    extern __shared__ char asm_raw[];
    // layout: ks[2] | vs[2] | qs | sc | jmax | jsum | jfac | tpos
    float* qs   = (float*)(asm_raw + 4 * KV_STAGE_B);
    float* sc   = qs + JG * 64;
    float* jmax = sc + JG * 128;
    float* jsum = jmax + JG;
    float* jfac = jsum + JG;
    int*   tpos = (int*)(jfac + JG);
    uint32_t sb = smem_u32(asm_raw);

    int grp = blockIdx.x % 9;
    int bh  = blockIdx.x / 9;
    int h = bh % NH, b = bh / NH;
    int tid = threadIdx.x;
    int j = tid >> 6;          // 0..4
    int e = tid & 63;

    if (tid < JG) {
        tpos[tid] = g_top[bh * NU + grp * JG + tid];
        jmax[tid] = -INFINITY;
        jsum[tid] = 0.f;
    }
    __syncthreads();
    qs[j * 64 + e] = g_qkv[((size_t)(b * NLQ + tpos[j])) * QKVS + h * NE + e];

    float cacc = 0.f;
    const size_t kvbase = (size_t)b * NLQ * QKVS + h * NE;
    const int NT = NLQ / 128;

    // issue K,V tile t into stage s
#define AISSUE(t, s) do {                                                      \
        int l0_ = (t) * 128;                                                   \
        uint32_t kdst = sb + (uint32_t)(s) * KV_STAGE_B;                       \
        uint32_t vdst = sb + 2u * KV_STAGE_B + (uint32_t)(s) * KV_STAGE_B;     \
        for (int i = tid; i < 2048; i += 320) {                                \
            int r_ = i >> 4, c4_ = i & 15;                                     \
            size_t go_ = kvbase + (size_t)(l0_ + r_) * QKVS + c4_ * 4;         \
            cp16(kdst + (uint32_t)i * 16, g_qkv + go_ + ND);                   \
            cp16(vdst + (uint32_t)i * 16, g_qkv + go_ + 2 * ND);               \
        }                                                                      \
        CP_COMMIT();                                                           \
    } while (0)

    AISSUE(0, 0);

#pragma unroll 1
    for (int t = 0; t < NT; t++) {
        CP_WAIT(0);
        __syncthreads();
        // prefetch t+1 into the other stage: its readers (tile t-1) passed bar
        if (t + 1 < NT)
            AISSUE(t + 1, (t + 1) & 1);
        const float* ks = (const float*)(asm_raw + (size_t)(t & 1) * KV_STAGE_B);
        const float* vs = (const float*)(asm_raw + 2 * KV_STAGE_B
                                         + (size_t)(t & 1) * KV_STAGE_B);

        // scores: 5*128 outputs
        for (int idx = tid; idx < JG * 128; idx += 320) {
            int jj = idx >> 7, ll = idx & 127;
            const float4* kr = (const float4*)(ks + ll * 64);
            const float4* qr = (const float4*)(qs + jj * 64);
            float s0 = 0.f, s1 = 0.f, s2 = 0.f, s3 = 0.f;
#pragma unroll
            for (int e4 = 0; e4 < 16; e4 += 4) {
                float4 a0 = kr[e4],     q0 = qr[e4];
                float4 a1 = kr[e4 + 1], q1 = qr[e4 + 1];
                float4 a2 = kr[e4 + 2], q2 = qr[e4 + 2];
                float4 a3 = kr[e4 + 3], q3 = qr[e4 + 3];
                s0 += a0.x * q0.x + a0.y * q0.y + a0.z * q0.z + a0.w * q0.w;
                s1 += a1.x * q1.x + a1.y * q1.y + a1.z * q1.z + a1.w * q1.w;
                s2 += a2.x * q2.x + a2.y * q2.y + a2.z * q2.z + a2.w * q2.w;
                s3 += a3.x * q3.x + a3.y * q3.y + a3.z * q3.z + a3.w * q3.w;
            }
            sc[jj * 128 + ll] = ((s0 + s1) + (s2 + s3)) * 0.125f;
        }
        __syncthreads();
        // per-j running max + rescale factor
        int w = tid >> 5, lane = tid & 31;
        if (w < JG) {
            float m = fmaxf(fmaxf(sc[w * 128 + lane], sc[w * 128 + lane + 32]),
                            fmaxf(sc[w * 128 + lane + 64], sc[w * 128 + lane + 96]));
#pragma unroll
            for (int o = 16; o > 0; o >>= 1)
                m = fmaxf(m, __shfl_xor_sync(0xffffffffu, m, o));
            if (lane == 0) {
                float old = jmax[w];
                float nm = fmaxf(old, m);
                jfac[w] = expf(old - nm);
                jmax[w] = nm;
            }
        }
        __syncthreads();
        for (int idx = tid; idx < JG * 128; idx += 320) {
            int jj = idx >> 7;
            sc[idx] = expf(sc[idx] - jmax[jj]);
        }
        __syncthreads();
        if (w < JG) {
            float s = sc[w * 128 + lane] + sc[w * 128 + lane + 32]
                    + sc[w * 128 + lane + 64] + sc[w * 128 + lane + 96];
#pragma unroll
            for (int o = 16; o > 0; o >>= 1)
                s += __shfl_xor_sync(0xffffffffu, s, o);
            if (lane == 0) jsum[w] = jsum[w] * jfac[w] + s;
        }
        // accumulate ctx with 4 independent chains
        {
            float a0 = 0.f, a1 = 0.f, a2 = 0.f, a3 = 0.f;
            const float* sj = sc + j * 128;
#pragma unroll 8
            for (int l = 0; l < 128; l += 4) {
                a0 += sj[l]     * vs[(l)     * 64 + e];
                a1 += sj[l + 1] * vs[(l + 1) * 64 + e];
                a2 += sj[l + 2] * vs[(l + 2) * 64 + e];
                a3 += sj[l + 3] * vs[(l + 3) * 64 + e];
            }
            cacc = cacc * jfac[j] + ((a0 + a1) + (a2 + a3));
        }
        __syncthreads();
    }
#undef AISSUE

    float u = cacc / jsum[j];
    size_t off = ((size_t)(b * NLQ + tpos[j])) * ND + h * NE + e;
    split_write(g_xhi, g_xlo, off, u);
}

// ------------- residual add + layernorm (+ split), float2 paths -------------
__global__ __launch_bounds__(256)
void add_ln_kernel(float* __restrict__ hbuf, const float* __restrict__ a,
                   const float* __restrict__ g, const float* __restrict__ bta) {
    size_t row = blockIdx.x;
    int t = threadIdx.x;
    float2 hv = *(const float2*)(hbuf + row * ND + t * 2);
    float2 av = *(const float2*)(a    + row * ND + t * 2);
    float x0 = hv.x + av.x;
    float x1 = hv.y + av.y;
    __shared__ float red[256];
    red[t] = x0 + x1; __syncthreads();
    for (int s = 128; s > 0; s >>= 1) {
        if (t < s) red[t] += red[t + s];
        __syncthreads();
    }
    float mean = red[0] * (1.0f / (float)ND);
    __syncthreads();
    float d0 = x0 - mean, d1 = x1 - mean;
    red[t] = d0 * d0 + d1 * d1; __syncthreads();
    for (int s = 128; s > 0; s >>= 1) {
        if (t < s) red[t] += red[t + s];
        __syncthreads();
    }
    float var = red[0] * (1.0f / (float)ND);
    float inv = 1.0f / sqrtf(var + 1e-5f);
    float2 gv = *(const float2*)(g   + t * 2);
    float2 bv = *(const float2*)(bta + t * 2);
    float o0 = d0 * inv * gv.x + bv.x;
    float o1 = d1 * inv * gv.y + bv.y;
    *(float2*)(hbuf + row * ND + t * 2) = make_float2(o0, o1);
    __nv_bfloat16 h0 = __float2bfloat16(o0), h1 = __float2bfloat16(o1);
    __nv_bfloat162 ph; ph.x = h0; ph.y = h1;
    __nv_bfloat162 pl;
    pl.x = __float2bfloat16(o0 - __bfloat162float(h0));
    pl.y = __float2bfloat16(o1 - __bfloat162float(h1));
    *(__nv_bfloat162*)(g_hhi + row * ND + t * 2) = ph;
    *(__nv_bfloat162*)(g_hlo + row * ND + t * 2) = pl;
}

// ------------------------------- final readout ------------------------------
__global__ void final_kernel(const float* __restrict__ Wf,
                             const float* __restrict__ bf, float* __restrict__ out) {
    int b = blockIdx.x;
    float acc = 0.f;
    for (int d = threadIdx.x; d < ND; d += 256)
        acc += g_h[(size_t)b * NLQ * ND + d] * Wf[d];
    __shared__ float red[256];
    red[threadIdx.x] = acc; __syncthreads();
    for (int s = 128; s > 0; s >>= 1) {
        if (threadIdx.x < s) red[threadIdx.x] += red[threadIdx.x + s];
        __syncthreads();
    }
    if (threadIdx.x == 0) out[b] = red[0] + bf[0];
}

// --------------------------------- launch -----------------------------------
extern "C" void kernel_launch(void* const* d_in, const int* in_sizes, int n_in,
                              void* d_out, int out_size) {
    (void)in_sizes; (void)n_in; (void)out_size;
    const float* x   = (const float*)d_in[0];
    const float* We  = (const float*)d_in[1];
    const float* be  = (const float*)d_in[2];
    const float* cls = (const float*)d_in[3];
    const float* Wq  = (const float*)d_in[4];
    const float* bq  = (const float*)d_in[5];
    const float* Wk  = (const float*)d_in[6];
    const float* bk  = (const float*)d_in[7];
    const float* Wv  = (const float*)d_in[8];
    const float* bv  = (const float*)d_in[9];
    const float* Wo  = (const float*)d_in[10];
    const float* bo  = (const float*)d_in[11];
    const float* g1  = (const float*)d_in[12];
    const float* b1  = (const float*)d_in[13];
    const float* g2  = (const float*)d_in[14];
    const float* b2  = (const float*)d_in[15];
    const float* W1  = (const float*)d_in[16];
    const float* bf1 = (const float*)d_in[17];
    const float* W2  = (const float*)d_in[18];
    const float* bf2 = (const float*)d_in[19];
    const float* Wf  = (const float*)d_in[20];
    const float* bf  = (const float*)d_in[21];

    float *h, *qkv, *tmp, *bqkv;
    __nv_bfloat16 *hhi, *hlo, *xhi, *xlo;
    __nv_bfloat16 *wqh, *wql, *woh, *wol, *w1h, *w1l, *w2h, *w2l;
    cudaGetSymbolAddress((void**)&h,    g_h);
    cudaGetSymbolAddress((void**)&qkv,  g_qkv);
    cudaGetSymbolAddress((void**)&tmp,  g_tmp);
    cudaGetSymbolAddress((void**)&bqkv, g_bqkv);
    cudaGetSymbolAddress((void**)&hhi,  g_hhi);
    cudaGetSymbolAddress((void**)&hlo,  g_hlo);
    cudaGetSymbolAddress((void**)&xhi,  g_xhi);
    cudaGetSymbolAddress((void**)&xlo,  g_xlo);
    cudaGetSymbolAddress((void**)&wqh,  g_wqkv_hi);
    cudaGetSymbolAddress((void**)&wql,  g_wqkv_lo);
    cudaGetSymbolAddress((void**)&woh,  g_wo_hi);
    cudaGetSymbolAddress((void**)&wol,  g_wo_lo);
    cudaGetSymbolAddress((void**)&w1h,  g_w1_hi);
    cudaGetSymbolAddress((void**)&w1l,  g_w1_lo);
    cudaGetSymbolAddress((void**)&w2h,  g_w2_hi);
    cudaGetSymbolAddress((void**)&w2l,  g_w2_lo);

    cudaFuncSetAttribute(gemm_mma_kernel,
                         cudaFuncAttributeMaxDynamicSharedMemorySize, GEMM_SMEM);
    cudaFuncSetAttribute(attn_fused_kernel,
                         cudaFuncAttributeMaxDynamicSharedMemorySize, ATTN_SMEM);

    const int Mrows = NB * NLQ;               // 8192

#define GEMM_F32(ah, al, bh, bl, bias, Cout, N, K, relu) \
    gemm_mma_kernel<<<dim3((N) / 128, Mrows / 128), 256, GEMM_SMEM>>>( \
        ah, al, bh, bl, bias, Cout, nullptr, nullptr, N, K, relu, 0)
#define GEMM_SPL(ah, al, bh, bl, bias, Hout, Lout, N, K, relu) \
    gemm_mma_kernel<<<dim3((N) / 128, Mrows / 128), 256, GEMM_SMEM>>>( \
        ah, al, bh, bl, bias, nullptr, Hout, Lout, N, K, relu, 1)

    presplit_kernel<<<dim3(2048, 12), 256>>>(Wq, Wk, Wv, Wo, W1, W2);
    biaspack_kernel<<<1, 512>>>(bq, bk, bv);
    embed_kernel<<<NB * NLQ, 256>>>(x, We, be, cls);

    for (int l = 0; l < NLAYERS; l++) {
        // ---- fused QKV projection (N=1536) ----
        GEMM_F32(hhi, hlo, wqh + (size_t)l * QKVS * ND, wql + (size_t)l * QKVS * ND,
                 bqkv + l * QKVS, qkv, QKVS, ND, 0);

        // ---- ProbSparse attention ----
        unsigned r0, r1;
        threefry2x32(0u, 42u, 0u, (unsigned)l, r0, r1);
        unsigned k2a, k2b;
        threefry2x32(r0, r1, 0u, 1u, k2a, k2b);
        rng_idx_kernel<<<(NLQ * NU + 255) / 256, 256>>>(k2a, k2b);
        qks_m_kernel<<<(NB * NH * NLQ * 32) / 256, 256>>>();
        topk_kernel<<<NB * NH, 256>>>();
        vmean_kernel<<<NB * NH, 256>>>();
        ctx_init_kernel<<<(NB * NLQ * ND + 255) / 256, 256>>>();
        attn_fused_kernel<<<NB * NH * 9, 320, ATTN_SMEM>>>();

        // ---- output projection + LN1 ----
        GEMM_F32(xhi, xlo, woh + (size_t)l * ND * ND, wol + (size_t)l * ND * ND,
                 bo + l * ND, tmp, ND, ND, 0);
        add_ln_kernel<<<Mrows, 256>>>(h, tmp, g1 + l * ND, b1 + l * ND);

        // ---- FFN + LN2 ----
        GEMM_SPL(hhi, hlo, w1h + (size_t)l * NDFF * ND, w1l + (size_t)l * NDFF * ND,
                 bf1 + l * NDFF, xhi, xlo, NDFF, ND, 1);
        GEMM_F32(xhi, xlo, w2h + (size_t)l * ND * NDFF, w2l + (size_t)l * ND * NDFF,
                 bf2 + l * ND, tmp, ND, NDFF, 0);
        add_ln_kernel<<<Mrows, 256>>>(h, tmp, g2 + l * ND, b2 + l * ND);
    }

    final_kernel<<<NB, 256>>>(Wf, bf, (float*)d_out);
#undef GEMM_F32
#undef GEMM_SPL
}

// round 17
// speedup vs baseline: 1.0991x; 1.0041x over previous
#include <cuda_runtime.h>
#include <cuda_bf16.h>
#include <math.h>
#include <stdint.h>

// ---------------------------------------------------------------------------
// CryptoInformer: 2-layer Informer encoder.
// GEMMs via mma.sync bf16 (HMMA) with 2-term bf16 split (hh+hl+lh).
// R17 (on top of R16 WIN): embed pos-enc rewritten as one fp64-range-reduced
// __sincosf per (sin,cos) pair (kills libm large-arg slow path); attention
// max/exp/sum fused into one warp-per-j pass (5 -> 4 barriers/tile).
// ---------------------------------------------------------------------------

#define NB 2
#define NS 4095
#define NLQ 4096          // L = S+1
#define NFIN 32
#define ND 512
#define NH 8
#define NE 64
#define NDFF 2048
#define NU 45
#define NLAYERS 2
#define JG 5              // queries per attention block (45 = 5*9)
#define QKVS 1536         // row stride of fused qkv buffer

// ------------------------- scratch (device globals) ------------------------
__device__ __align__(16) float g_h  [NB*NLQ*ND];
__device__ __align__(16) float g_qkv[NB*NLQ*QKVS];   // [row][q|k|v]
__device__ __align__(16) float g_tmp[NB*NLQ*ND];
__device__ float g_M  [NB*NH*NLQ];
__device__ float g_vmean[NB*NH*NE];
__device__ int   g_idx[NLQ*NU];
__device__ int   g_top[NB*NH*NU];
// bf16 split buffers (activations)
__device__ __align__(16) __nv_bfloat16 g_hhi[NB*NLQ*ND];
__device__ __align__(16) __nv_bfloat16 g_hlo[NB*NLQ*ND];
__device__ __align__(16) __nv_bfloat16 g_xhi[NB*NLQ*NDFF];   // ctx split, then y1 split
__device__ __align__(16) __nv_bfloat16 g_xlo[NB*NLQ*NDFF];
// bf16 split buffers (weights, pre-split once per call)
__device__ __align__(16) __nv_bfloat16 g_wqkv_hi[NLAYERS*QKVS*ND];
__device__ __align__(16) __nv_bfloat16 g_wqkv_lo[NLAYERS*QKVS*ND];
__device__ __align__(16) __nv_bfloat16 g_wo_hi[NLAYERS*ND*ND];
__device__ __align__(16) __nv_bfloat16 g_wo_lo[NLAYERS*ND*ND];
__device__ __align__(16) __nv_bfloat16 g_w1_hi[NLAYERS*NDFF*ND];
__device__ __align__(16) __nv_bfloat16 g_w1_lo[NLAYERS*NDFF*ND];
__device__ __align__(16) __nv_bfloat16 g_w2_hi[NLAYERS*ND*NDFF];
__device__ __align__(16) __nv_bfloat16 g_w2_lo[NLAYERS*ND*NDFF];
__device__ float g_bqkv[NLAYERS*QKVS];

__device__ __forceinline__ void split_write(__nv_bfloat16* hi, __nv_bfloat16* lo,
                                            size_t off, float v) {
    __nv_bfloat16 h = __float2bfloat16(v);
    hi[off] = h;
    lo[off] = __float2bfloat16(v - __bfloat162float(h));
}

// ------------------------------ threefry2x32 --------------------------------
__host__ __device__ __forceinline__ unsigned tf_rotl(unsigned x, int d) {
    return (x << d) | (x >> (32 - d));
}
__host__ __device__ inline void threefry2x32(unsigned k0, unsigned k1,
                                             unsigned x0, unsigned x1,
                                             unsigned &o0, unsigned &o1) {
    unsigned ks2 = k0 ^ k1 ^ 0x1BD11BDAu;
    unsigned v0 = x0 + k0;
    unsigned v1 = x1 + k1;
#define TF_R(r) { v0 += v1; v1 = tf_rotl(v1, r); v1 ^= v0; }
    TF_R(13) TF_R(15) TF_R(26) TF_R(6)
    v0 += k1;  v1 += ks2 + 1u;
    TF_R(17) TF_R(29) TF_R(16) TF_R(24)
    v0 += ks2; v1 += k0 + 2u;
    TF_R(13) TF_R(15) TF_R(26) TF_R(6)
    v0 += k0;  v1 += k1 + 3u;
    TF_R(17) TF_R(29) TF_R(16) TF_R(24)
    v0 += k1;  v1 += ks2 + 4u;
    TF_R(13) TF_R(15) TF_R(26) TF_R(6)
    v0 += ks2; v1 += k0 + 5u;
#undef TF_R
    o0 = v0; o1 = v1;
}

__global__ void rng_idx_kernel(unsigned k2a, unsigned k2b) {
    int j = blockIdx.x * blockDim.x + threadIdx.x;
    if (j >= NLQ * NU) return;
    unsigned w0, w1;
    threefry2x32(k2a, k2b, 0u, (unsigned)j, w0, w1);
    g_idx[j] = (int)((w0 ^ w1) & 0xFFFu);
}

// ------------------- one-shot weight split (12 segments) --------------------
__global__ void presplit_kernel(const float* __restrict__ Wq,
                                const float* __restrict__ Wk,
                                const float* __restrict__ Wv,
                                const float* __restrict__ Wo,
                                const float* __restrict__ W1,
                                const float* __restrict__ W2) {
    int seg = blockIdx.y;
    int mat = seg >> 1, l = seg & 1;
    const float* src;
    __nv_bfloat16 *hi, *lo;
    size_t off; int n2;
    const int SQ = ND * ND;        // 262144
    const int SF = NDFF * ND;      // 1048576
    switch (mat) {
        case 0: src = Wq + (size_t)l * SQ; hi = g_wqkv_hi; lo = g_wqkv_lo;
                off = (size_t)l * (QKVS * ND);             n2 = SQ / 2; break;
        case 1: src = Wk + (size_t)l * SQ; hi = g_wqkv_hi; lo = g_wqkv_lo;
                off = (size_t)l * (QKVS * ND) + SQ;        n2 = SQ / 2; break;
        case 2: src = Wv + (size_t)l * SQ; hi = g_wqkv_hi; lo = g_wqkv_lo;
                off = (size_t)l * (QKVS * ND) + 2 * SQ;    n2 = SQ / 2; break;
        case 3: src = Wo + (size_t)l * SQ; hi = g_wo_hi;   lo = g_wo_lo;
                off = (size_t)l * SQ;                      n2 = SQ / 2; break;
        case 4: src = W1 + (size_t)l * SF; hi = g_w1_hi;   lo = g_w1_lo;
                off = (size_t)l * SF;                      n2 = SF / 2; break;
        default: src = W2 + (size_t)l * SF; hi = g_w2_hi;  lo = g_w2_lo;
                off = (size_t)l * SF;                      n2 = SF / 2; break;
    }
    int i = blockIdx.x * blockDim.x + threadIdx.x;
    if (i >= n2) return;
    float2 v = ((const float2*)src)[i];
    __nv_bfloat16 h0 = __float2bfloat16(v.x);
    __nv_bfloat16 h1 = __float2bfloat16(v.y);
    __nv_bfloat162 hh; hh.x = h0; hh.y = h1;
    __nv_bfloat162 ll;
    ll.x = __float2bfloat16(v.x - __bfloat162float(h0));
    ll.y = __float2bfloat16(v.y - __bfloat162float(h1));
    ((__nv_bfloat162*)(hi + off))[i] = hh;
    ((__nv_bfloat162*)(lo + off))[i] = ll;
}

__global__ void biaspack_kernel(const float* __restrict__ bq,
                                const float* __restrict__ bk,
                                const float* __restrict__ bv) {
    int t = threadIdx.x;   // 512
#pragma unroll
    for (int l = 0; l < NLAYERS; l++) {
        g_bqkv[l * QKVS + t]        = bq[l * ND + t];
        g_bqkv[l * QKVS + ND + t]   = bk[l * ND + t];
        g_bqkv[l * QKVS + 2*ND + t] = bv[l * ND + t];
    }
}

// ------------------------------ embed + pos enc -----------------------------
// One thread per (sin,cos) pair: one expf + one fp64-range-reduced __sincosf.
__global__ void embed_kernel(const float* __restrict__ x,
                             const float* __restrict__ We,
                             const float* __restrict__ be,
                             const float* __restrict__ cls) {
    int bt = blockIdx.x;                 // 0..NB*NLQ-1
    int b = bt / NLQ, t = bt % NLQ;
    __shared__ float xs[NFIN];
    if (t > 0 && threadIdx.x < NFIN)
        xs[threadIdx.x] = x[((size_t)b * NS + (t - 1)) * NFIN + threadIdx.x];
    __syncthreads();
    const float cexp = (float)(-9.210340371976184 / 512.0);  // -ln(1e4)/D
    int p = threadIdx.x;                 // pair index 0..255
    int d0 = p * 2, d1 = d0 + 1;
    float v0, v1;
    if (t == 0) {
        v0 = cls[d0];
        v1 = cls[d1];
    } else {
        float a0 = be[d0], a1 = be[d1];
        const float* w0 = We + (size_t)d0 * NFIN;
        const float* w1 = We + (size_t)d1 * NFIN;
#pragma unroll
        for (int f = 0; f < NFIN; f++) {
            float xv = xs[f];
            a0 += xv * w0[f];
            a1 += xv * w1[f];
        }
        v0 = a0; v1 = a1;
    }
    float freq = expf((float)d0 * cexp);
    // arg = t*freq, reduced mod 2*pi in fp64 (exact enough; arg <= 4095)
    double arg = (double)t * (double)freq;
    const double TWO_PI = 6.283185307179586476925286766559;
    double k = floor(arg * (1.0 / TWO_PI));
    float ra = (float)(arg - k * TWO_PI);
    float s, c;
    __sincosf(ra, &s, &c);
    float o0 = v0 + s;
    float o1 = v1 + c;
    size_t off = (size_t)bt * ND + d0;
    *(float2*)(g_h + off) = make_float2(o0, o1);
    __nv_bfloat16 h0 = __float2bfloat16(o0), h1 = __float2bfloat16(o1);
    __nv_bfloat162 ph; ph.x = h0; ph.y = h1;
    __nv_bfloat162 pl;
    pl.x = __float2bfloat16(o0 - __bfloat162float(h0));
    pl.y = __float2bfloat16(o1 - __bfloat162float(h1));
    *(__nv_bfloat162*)(g_hhi + off) = ph;
    *(__nv_bfloat162*)(g_hlo + off) = pl;
}

// ----------------------------- mma.sync helpers -----------------------------
__device__ __forceinline__ uint32_t smem_u32(const void* p) {
    uint32_t a;
    asm("{ .reg .u64 t; cvta.to.shared.u64 t, %1; cvt.u32.u64 %0, t; }" : "=r"(a) : "l"(p));
    return a;
}
__device__ __forceinline__ void cp16(uint32_t dst, const void* src) {
    asm volatile("cp.async.cg.shared.global [%0], [%1], 16;" :: "r"(dst), "l"(src));
}
#define CP_COMMIT() asm volatile("cp.async.commit_group;" ::: "memory")
#define CP_WAIT(n)  asm volatile("cp.async.wait_group %0;" :: "n"(n) : "memory")

#define LDMX4(r, a) \
    asm volatile("ldmatrix.sync.aligned.m8n8.x4.shared.b16 {%0,%1,%2,%3}, [%4];" \
        : "=r"((r)[0]), "=r"((r)[1]), "=r"((r)[2]), "=r"((r)[3]) : "r"(a))

#define MMA16816(c, a, b0, b1) \
    asm volatile("mma.sync.aligned.m16n8k16.row.col.f32.bf16.bf16.f32 " \
        "{%0,%1,%2,%3}, {%4,%5,%6,%7}, {%8,%9}, {%0,%1,%2,%3};" \
        : "+f"((c)[0]), "+f"((c)[1]), "+f"((c)[2]), "+f"((c)[3]) \
        : "r"((a)[0]), "r"((a)[1]), "r"((a)[2]), "r"((a)[3]), "r"(b0), "r"(b1))

// ----------------------- bf16-split HMMA GEMM (R10 proven) ------------------
// out = (Ah+Al)[M,K] @ (Bh+Bl)[N,K]^T + bias[N]  (drop Al*Bl), opt relu.
// 128x128 CTA, 256 threads (2x4 warps, 64x32 warp tiles), K-chunk 32,
// 2-stage cp.async, 1 barrier/chunk. Row stride 80B.
#define SROWB 80                      // bytes per smem row
#define TILE_B (128 * SROWB)          // 10240 bytes per tile
#define STAGE_B (4 * TILE_B)          // 40960: AH AL BH BL
#define GEMM_SMEM (2 * STAGE_B)       // 81920
__global__ __launch_bounds__(256, 2)
void gemm_mma_kernel(const __nv_bfloat16* __restrict__ Ah,
                     const __nv_bfloat16* __restrict__ Al,
                     const __nv_bfloat16* __restrict__ Bh,
                     const __nv_bfloat16* __restrict__ Bl,
                     const float* __restrict__ bias, float* __restrict__ C,
                     __nv_bfloat16* __restrict__ Chi, __nv_bfloat16* __restrict__ Clo,
                     int Ndim, int Kdim, int relu, int mode) {
    extern __shared__ char smem[];
    uint32_t sb = smem_u32(smem);
    int tid = threadIdx.x, lane = tid & 31, w = tid >> 5;
    int wm = w & 1, wn = w >> 1;                 // 2 x 4 warp grid
    int bm = blockIdx.y * 128, bn = blockIdx.x * 128;

    float acc[4][4][4];
#pragma unroll
    for (int i = 0; i < 4; i++)
#pragma unroll
        for (int j = 0; j < 4; j++)
#pragma unroll
            for (int r = 0; r < 4; r++) acc[i][j][r] = 0.f;

    const int nch = Kdim >> 5;

#define ISSUE(kc, soff) do {                                                   \
        _Pragma("unroll")                                                      \
        for (int j = 0; j < 2; j++) {                                          \
            int id = tid + j * 256;                                            \
            int row = id >> 2, cc = id & 3;                                    \
            uint32_t dst = sb + (soff) + (uint32_t)(row * SROWB + cc * 16);    \
            size_t ga = (size_t)(bm + row) * Kdim + (kc) + cc * 8;             \
            size_t gb = (size_t)(bn + row) * Kdim + (kc) + cc * 8;             \
            cp16(dst,              Ah + ga);                                   \
            cp16(dst + TILE_B,     Al + ga);                                   \
            cp16(dst + 2 * TILE_B, Bh + gb);                                   \
            cp16(dst + 3 * TILE_B, Bl + gb);                                   \
        }                                                                      \
        CP_COMMIT();                                                           \
    } while (0)

    ISSUE(0, 0);

    for (int c = 0; c < nch; c++) {
        CP_WAIT(0);
        __syncthreads();
        if (c + 1 < nch)
            ISSUE((c + 1) << 5, (uint32_t)((c + 1) & 1) * STAGE_B);
        uint32_t soff = (uint32_t)(c & 1) * STAGE_B;

#pragma unroll
        for (int ks = 0; ks < 32; ks += 16) {
            uint32_t colb = (uint32_t)((ks + ((lane >> 4) << 3)) * 2);
            uint32_t ah[4][4], al[4][4];
#pragma unroll
            for (int mt = 0; mt < 4; mt++) {
                uint32_t ad = sb + soff
                            + (uint32_t)((wm * 64 + mt * 16 + (lane & 15)) * SROWB) + colb;
                LDMX4(ah[mt], ad);
                LDMX4(al[mt], ad + TILE_B);
            }
            uint32_t bh[2][4], bl[2][4];
#pragma unroll
            for (int p = 0; p < 2; p++) {
                uint32_t bd = sb + soff + 2 * TILE_B
                            + (uint32_t)((wn * 32 + p * 16 + (lane & 15)) * SROWB) + colb;
                LDMX4(bh[p], bd);
                LDMX4(bl[p], bd + TILE_B);
            }
#pragma unroll
            for (int mt = 0; mt < 4; mt++)
#pragma unroll
                for (int nt = 0; nt < 4; nt++) {
                    int p = nt >> 1, s = nt & 1;
                    MMA16816(acc[mt][nt], ah[mt], bh[p][s], bh[p][s + 2]);
                    MMA16816(acc[mt][nt], ah[mt], bl[p][s], bl[p][s + 2]);
                    MMA16816(acc[mt][nt], al[mt], bh[p][s], bh[p][s + 2]);
                }
        }
    }
#undef ISSUE

    // epilogue
#pragma unroll
    for (int mt = 0; mt < 4; mt++) {
        int m0 = bm + wm * 64 + mt * 16 + (lane >> 2);
#pragma unroll
        for (int nt = 0; nt < 4; nt++) {
            int n0 = bn + wn * 32 + nt * 8 + (lane & 3) * 2;
            float b0 = bias[n0], b1 = bias[n0 + 1];
            float v0 = acc[mt][nt][0] + b0, v1 = acc[mt][nt][1] + b1;
            float v2 = acc[mt][nt][2] + b0, v3 = acc[mt][nt][3] + b1;
            if (relu) {
                v0 = fmaxf(v0, 0.f); v1 = fmaxf(v1, 0.f);
                v2 = fmaxf(v2, 0.f); v3 = fmaxf(v3, 0.f);
            }
            if (mode == 0) {
                *(float2*)(C + (size_t)m0 * Ndim + n0)       = make_float2(v0, v1);
                *(float2*)(C + (size_t)(m0 + 8) * Ndim + n0) = make_float2(v2, v3);
            } else {
                size_t o0 = (size_t)m0 * Ndim + n0;
                size_t o1 = (size_t)(m0 + 8) * Ndim + n0;
                __nv_bfloat16 h0 = __float2bfloat16(v0), h1 = __float2bfloat16(v1);
                __nv_bfloat16 h2 = __float2bfloat16(v2), h3 = __float2bfloat16(v3);
                __nv_bfloat162 p0; p0.x = h0; p0.y = h1;
                __nv_bfloat162 p1; p1.x = h2; p1.y = h3;
                *(__nv_bfloat162*)(Chi + o0) = p0;
                *(__nv_bfloat162*)(Chi + o1) = p1;
                __nv_bfloat162 q0, q1;
                q0.x = __float2bfloat16(v0 - __bfloat162float(h0));
                q0.y = __float2bfloat16(v1 - __bfloat162float(h1));
                q1.x = __float2bfloat16(v2 - __bfloat162float(h2));
                q1.y = __float2bfloat16(v3 - __bfloat162float(h3));
                *(__nv_bfloat162*)(Clo + o0) = q0;
                *(__nv_bfloat162*)(Clo + o1) = q1;
            }
        }
    }
}

// -------------------- sparse QK sampling -> M measure -----------------------
__global__ void qks_m_kernel() {
    int gw = (blockIdx.x * blockDim.x + threadIdx.x) >> 5;
    int lane = threadIdx.x & 31;
    if (gw >= NB * NH * NLQ) return;
    int l  = gw % NLQ;
    int bh = gw / NLQ;
    int h  = bh % NH, b = bh / NH;
    const float* qrow = g_qkv + ((size_t)(b * NLQ + l)) * QKVS + h * NE;
    float2 qv = *(const float2*)(qrow + lane * 2);
    const int* idxp = g_idx + l * NU;
    const float* kbase = g_qkv + (size_t)b * NLQ * QKVS + ND + h * NE + lane * 2;
    float mx = -INFINITY, sm = 0.f;
#pragma unroll 1
    for (int j0 = 0; j0 < NU; j0 += 5) {
        int ki[5];
#pragma unroll
        for (int u = 0; u < 5; u++) ki[u] = idxp[j0 + u];
        float2 kv[5];
#pragma unroll
        for (int u = 0; u < 5; u++)
            kv[u] = *(const float2*)(kbase + (size_t)ki[u] * QKVS);
        float r[5];
#pragma unroll
        for (int u = 0; u < 5; u++) {
            float p = qv.x * kv[u].x + qv.y * kv[u].y;
#pragma unroll
            for (int o = 16; o > 0; o >>= 1)
                p += __shfl_xor_sync(0xffffffffu, p, o);
            r[u] = p;
        }
#pragma unroll
        for (int u = 0; u < 5; u++) {   // in-order accumulate (exact)
            mx = fmaxf(mx, r[u]);
            sm += r[u];
        }
    }
    if (lane == 0) g_M[gw] = mx - sm * (1.0f / (float)NLQ);
}

// ------------------------- top-k (k=45) per (b,h) ---------------------------
__global__ void topk_kernel() {
    int bh = blockIdx.x;
    __shared__ float sv[NLQ];
    __shared__ float rv[256];
    __shared__ int   ri[256];
    const float* m = g_M + (size_t)bh * NLQ;
    for (int i = threadIdx.x; i < NLQ; i += blockDim.x) sv[i] = m[i];
    __syncthreads();
    for (int it = 0; it < NU; it++) {
        float bv = -INFINITY; int bi = 0x7fffffff;
        for (int i = threadIdx.x; i < NLQ; i += blockDim.x) {
            float vv = sv[i];
            if (vv > bv) { bv = vv; bi = i; }
        }
        rv[threadIdx.x] = bv; ri[threadIdx.x] = bi;
        __syncthreads();
        for (int s = 128; s > 0; s >>= 1) {
            if (threadIdx.x < s) {
                float ov = rv[threadIdx.x + s]; int oi = ri[threadIdx.x + s];
                if (ov > rv[threadIdx.x] ||
                    (ov == rv[threadIdx.x] && oi < ri[threadIdx.x])) {
                    rv[threadIdx.x] = ov; ri[threadIdx.x] = oi;
                }
            }
            __syncthreads();
        }
        if (threadIdx.x == 0) {
            g_top[bh * NU + it] = ri[0];
            sv[ri[0]] = -INFINITY;
        }
        __syncthreads();
    }
}

// ------------------------------ v mean per (b,h) ----------------------------
__global__ void vmean_kernel() {
    int bh = blockIdx.x; int b = bh / NH, h = bh % NH;
    int e = threadIdx.x & 63, part = threadIdx.x >> 6;
    float acc = 0.f;
    for (int l = part; l < NLQ; l += 4)
        acc += g_qkv[((size_t)(b * NLQ + l)) * QKVS + 2*ND + h * NE + e];
    __shared__ float sp[4][64];
    sp[part][e] = acc;
    __syncthreads();
    if (part == 0)
        g_vmean[bh * NE + e] =
            (sp[0][e] + sp[1][e] + sp[2][e] + sp[3][e]) * (1.0f / (float)NLQ);
}

// ctx default = vmean broadcast, written as bf16 hi/lo split
__global__ void ctx_init_kernel() {
    size_t i = (size_t)blockIdx.x * blockDim.x + threadIdx.x;
    if (i >= (size_t)NB * NLQ * ND) return;
    int d = (int)(i % ND);
    int b = (int)(i / ((size_t)NLQ * ND));
    float vv = g_vmean[(b * NH + (d >> 6)) * NE + (d & 63)];
    split_write(g_xhi, g_xlo, i, vv);
}

// ---- flash-style attention, double-buffered cp.async K/V tile loads --------
// block = (b,h, group of 5 top queries); 320 threads. Fused max/exp/sum.
#define KV_STAGE_B (128 * 64 * 4)                 // 32768 bytes per tensor/stage
#define ATTN_SMEM (4 * KV_STAGE_B + JG*64*4 + JG*128*4 + 4*JG*4 + 64)
__global__ __launch_bounds__(320)
void attn_fused_kernel() {
    extern __shared__ char asm_raw[];
    // layout: ks[2] | vs[2] | qs | sc | jmax | jsum | jfac | tpos
    float* qs   = (float*)(asm_raw + 4 * KV_STAGE_B);
    float* sc   = qs + JG * 64;
    float* jmax = sc + JG * 128;
    float* jsum = jmax + JG;
    float* jfac = jsum + JG;
    int*   tpos = (int*)(jfac + JG);
    uint32_t sb = smem_u32(asm_raw);

    int grp = blockIdx.x % 9;
    int bh  = blockIdx.x / 9;
    int h = bh % NH, b = bh / NH;
    int tid = threadIdx.x;
    int j = tid >> 6;          // 0..4
    int e = tid & 63;

    if (tid < JG) {
        tpos[tid] = g_top[bh * NU + grp * JG + tid];
        jmax[tid] = -INFINITY;
        jsum[tid] = 0.f;
    }
    __syncthreads();
    qs[j * 64 + e] = g_qkv[((size_t)(b * NLQ + tpos[j])) * QKVS + h * NE + e];

    float cacc = 0.f;
    const size_t kvbase = (size_t)b * NLQ * QKVS + h * NE;
    const int NT = NLQ / 128;

    // issue K,V tile t into stage s
#define AISSUE(t, s) do {                                                      \
        int l0_ = (t) * 128;                                                   \
        uint32_t kdst = sb + (uint32_t)(s) * KV_STAGE_B;                       \
        uint32_t vdst = sb + 2u * KV_STAGE_B + (uint32_t)(s) * KV_STAGE_B;     \
        for (int i = tid; i < 2048; i += 320) {                                \
            int r_ = i >> 4, c4_ = i & 15;                                     \
            size_t go_ = kvbase + (size_t)(l0_ + r_) * QKVS + c4_ * 4;         \
            cp16(kdst + (uint32_t)i * 16, g_qkv + go_ + ND);                   \
            cp16(vdst + (uint32_t)i * 16, g_qkv + go_ + 2 * ND);               \
        }                                                                      \
        CP_COMMIT();                                                           \
    } while (0)

    AISSUE(0, 0);

#pragma unroll 1
    for (int t = 0; t < NT; t++) {
        CP_WAIT(0);
        __syncthreads();
        // prefetch t+1 into the other stage: its readers (tile t-1) passed bar
        if (t + 1 < NT)
            AISSUE(t + 1, (t + 1) & 1);
        const float* ks = (const float*)(asm_raw + (size_t)(t & 1) * KV_STAGE_B);
        const float* vs = (const float*)(asm_raw + 2 * KV_STAGE_B
                                         + (size_t)(t & 1) * KV_STAGE_B);

        // scores: 5*128 outputs
        for (int idx = tid; idx < JG * 128; idx += 320) {
            int jj = idx >> 7, ll = idx & 127;
            const float4* kr = (const float4*)(ks + ll * 64);
            const float4* qr = (const float4*)(qs + jj * 64);
            float s0 = 0.f, s1 = 0.f, s2 = 0.f, s3 = 0.f;
#pragma unroll
            for (int e4 = 0; e4 < 16; e4 += 4) {
                float4 a0 = kr[e4],     q0 = qr[e4];
                float4 a1 = kr[e4 + 1], q1 = qr[e4 + 1];
                float4 a2 = kr[e4 + 2], q2 = qr[e4 + 2];
                float4 a3 = kr[e4 + 3], q3 = qr[e4 + 3];
                s0 += a0.x * q0.x + a0.y * q0.y + a0.z * q0.z + a0.w * q0.w;
                s1 += a1.x * q1.x + a1.y * q1.y + a1.z * q1.z + a1.w * q1.w;
                s2 += a2.x * q2.x + a2.y * q2.y + a2.z * q2.z + a2.w * q2.w;
                s3 += a3.x * q3.x + a3.y * q3.y + a3.z * q3.z + a3.w * q3.w;
            }
            sc[jj * 128 + ll] = ((s0 + s1) + (s2 + s3)) * 0.125f;
        }
        __syncthreads();
        // fused per-j max + exp + sum (warp w handles j = w)
        int w = tid >> 5, lane = tid & 31;
        if (w < JG) {
            float v0 = sc[w * 128 + lane],      v1 = sc[w * 128 + lane + 32];
            float v2 = sc[w * 128 + lane + 64], v3 = sc[w * 128 + lane + 96];
            float m = fmaxf(fmaxf(v0, v1), fmaxf(v2, v3));
#pragma unroll
            for (int o = 16; o > 0; o >>= 1)
                m = fmaxf(m, __shfl_xor_sync(0xffffffffu, m, o));
            float oldm = jmax[w];
            float nm = fmaxf(oldm, m);
            float fac = expf(oldm - nm);
            float e0 = expf(v0 - nm), e1 = expf(v1 - nm);
            float e2 = expf(v2 - nm), e3 = expf(v3 - nm);
            sc[w * 128 + lane]      = e0; sc[w * 128 + lane + 32] = e1;
            sc[w * 128 + lane + 64] = e2; sc[w * 128 + lane + 96] = e3;
            float s = (e0 + e1) + (e2 + e3);
#pragma unroll
            for (int o = 16; o > 0; o >>= 1)
                s += __shfl_xor_sync(0xffffffffu, s, o);
            if (lane == 0) {
                jmax[w] = nm;
                jfac[w] = fac;
                jsum[w] = jsum[w] * fac + s;
            }
        }
        __syncthreads();
        // accumulate ctx with 4 independent chains
        {
            float a0 = 0.f, a1 = 0.f, a2 = 0.f, a3 = 0.f;
            const float* sj = sc + j * 128;
#pragma unroll 8
            for (int l = 0; l < 128; l += 4) {
                a0 += sj[l]     * vs[(l)     * 64 + e];
                a1 += sj[l + 1] * vs[(l + 1) * 64 + e];
                a2 += sj[l + 2] * vs[(l + 2) * 64 + e];
                a3 += sj[l + 3] * vs[(l + 3) * 64 + e];
            }
            cacc = cacc * jfac[j] + ((a0 + a1) + (a2 + a3));
        }
        __syncthreads();
    }
#undef AISSUE

    float u = cacc / jsum[j];
    size_t off = ((size_t)(b * NLQ + tpos[j])) * ND + h * NE + e;
    split_write(g_xhi, g_xlo, off, u);
}

// ------------- residual add + layernorm (+ split), float2 paths -------------
__global__ __launch_bounds__(256)
void add_ln_kernel(float* __restrict__ hbuf, const float* __restrict__ a,
                   const float* __restrict__ g, const float* __restrict__ bta) {
    size_t row = blockIdx.x;
    int t = threadIdx.x;
    float2 hv = *(const float2*)(hbuf + row * ND + t * 2);
    float2 av = *(const float2*)(a    + row * ND + t * 2);
    float x0 = hv.x + av.x;
    float x1 = hv.y + av.y;
    __shared__ float red[256];
    red[t] = x0 + x1; __syncthreads();
    for (int s = 128; s > 0; s >>= 1) {
        if (t < s) red[t] += red[t + s];
        __syncthreads();
    }
    float mean = red[0] * (1.0f / (float)ND);
    __syncthreads();
    float d0 = x0 - mean, d1 = x1 - mean;
    red[t] = d0 * d0 + d1 * d1; __syncthreads();
    for (int s = 128; s > 0; s >>= 1) {
        if (t < s) red[t] += red[t + s];
        __syncthreads();
    }
    float var = red[0] * (1.0f / (float)ND);
    float inv = 1.0f / sqrtf(var + 1e-5f);
    float2 gv = *(const float2*)(g   + t * 2);
    float2 bv = *(const float2*)(bta + t * 2);
    float o0 = d0 * inv * gv.x + bv.x;
    float o1 = d1 * inv * gv.y + bv.y;
    *(float2*)(hbuf + row * ND + t * 2) = make_float2(o0, o1);
    __nv_bfloat16 h0 = __float2bfloat16(o0), h1 = __float2bfloat16(o1);
    __nv_bfloat162 ph; ph.x = h0; ph.y = h1;
    __nv_bfloat162 pl;
    pl.x = __float2bfloat16(o0 - __bfloat162float(h0));
    pl.y = __float2bfloat16(o1 - __bfloat162float(h1));
    *(__nv_bfloat162*)(g_hhi + row * ND + t * 2) = ph;
    *(__nv_bfloat162*)(g_hlo + row * ND + t * 2) = pl;
}

// ------------------------------- final readout ------------------------------
__global__ void final_kernel(const float* __restrict__ Wf,
                             const float* __restrict__ bf, float* __restrict__ out) {
    int b = blockIdx.x;
    float acc = 0.f;
    for (int d = threadIdx.x; d < ND; d += 256)
        acc += g_h[(size_t)b * NLQ * ND + d] * Wf[d];
    __shared__ float red[256];
    red[threadIdx.x] = acc; __syncthreads();
    for (int s = 128; s > 0; s >>= 1) {
        if (threadIdx.x < s) red[threadIdx.x] += red[threadIdx.x + s];
        __syncthreads();
    }
    if (threadIdx.x == 0) out[b] = red[0] + bf[0];
}

// --------------------------------- launch -----------------------------------
extern "C" void kernel_launch(void* const* d_in, const int* in_sizes, int n_in,
                              void* d_out, int out_size) {
    (void)in_sizes; (void)n_in; (void)out_size;
    const float* x   = (const float*)d_in[0];
    const float* We  = (const float*)d_in[1];
    const float* be  = (const float*)d_in[2];
    const float* cls = (const float*)d_in[3];
    const float* Wq  = (const float*)d_in[4];
    const float* bq  = (const float*)d_in[5];
    const float* Wk  = (const float*)d_in[6];
    const float* bk  = (const float*)d_in[7];
    const float* Wv  = (const float*)d_in[8];
    const float* bv  = (const float*)d_in[9];
    const float* Wo  = (const float*)d_in[10];
    const float* bo  = (const float*)d_in[11];
    const float* g1  = (const float*)d_in[12];
    const float* b1  = (const float*)d_in[13];
    const float* g2  = (const float*)d_in[14];
    const float* b2  = (const float*)d_in[15];
    const float* W1  = (const float*)d_in[16];
    const float* bf1 = (const float*)d_in[17];
    const float* W2  = (const float*)d_in[18];
    const float* bf2 = (const float*)d_in[19];
    const float* Wf  = (const float*)d_in[20];
    const float* bf  = (const float*)d_in[21];

    float *h, *qkv, *tmp, *bqkv;
    __nv_bfloat16 *hhi, *hlo, *xhi, *xlo;
    __nv_bfloat16 *wqh, *wql, *woh, *wol, *w1h, *w1l, *w2h, *w2l;
    cudaGetSymbolAddress((void**)&h,    g_h);
    cudaGetSymbolAddress((void**)&qkv,  g_qkv);
    cudaGetSymbolAddress((void**)&tmp,  g_tmp);
    cudaGetSymbolAddress((void**)&bqkv, g_bqkv);
    cudaGetSymbolAddress((void**)&hhi,  g_hhi);
    cudaGetSymbolAddress((void**)&hlo,  g_hlo);
    cudaGetSymbolAddress((void**)&xhi,  g_xhi);
    cudaGetSymbolAddress((void**)&xlo,  g_xlo);
    cudaGetSymbolAddress((void**)&wqh,  g_wqkv_hi);
    cudaGetSymbolAddress((void**)&wql,  g_wqkv_lo);
    cudaGetSymbolAddress((void**)&woh,  g_wo_hi);
    cudaGetSymbolAddress((void**)&wol,  g_wo_lo);
    cudaGetSymbolAddress((void**)&w1h,  g_w1_hi);
    cudaGetSymbolAddress((void**)&w1l,  g_w1_lo);
    cudaGetSymbolAddress((void**)&w2h,  g_w2_hi);
    cudaGetSymbolAddress((void**)&w2l,  g_w2_lo);

    cudaFuncSetAttribute(gemm_mma_kernel,
                         cudaFuncAttributeMaxDynamicSharedMemorySize, GEMM_SMEM);
    cudaFuncSetAttribute(attn_fused_kernel,
                         cudaFuncAttributeMaxDynamicSharedMemorySize, ATTN_SMEM);

    const int Mrows = NB * NLQ;               // 8192

#define GEMM_F32(ah, al, bh, bl, bias, Cout, N, K, relu) \
    gemm_mma_kernel<<<dim3((N) / 128, Mrows / 128), 256, GEMM_SMEM>>>( \
        ah, al, bh, bl, bias, Cout, nullptr, nullptr, N, K, relu, 0)
#define GEMM_SPL(ah, al, bh, bl, bias, Hout, Lout, N, K, relu) \
    gemm_mma_kernel<<<dim3((N) / 128, Mrows / 128), 256, GEMM_SMEM>>>( \
        ah, al, bh, bl, bias, nullptr, Hout, Lout, N, K, relu, 1)

    presplit_kernel<<<dim3(2048, 12), 256>>>(Wq, Wk, Wv, Wo, W1, W2);
    biaspack_kernel<<<1, 512>>>(bq, bk, bv);
    embed_kernel<<<NB * NLQ, 256>>>(x, We, be, cls);

    for (int l = 0; l < NLAYERS; l++) {
        // ---- fused QKV projection (N=1536) ----
        GEMM_F32(hhi, hlo, wqh + (size_t)l * QKVS * ND, wql + (size_t)l * QKVS * ND,
                 bqkv + l * QKVS, qkv, QKVS, ND, 0);

        // ---- ProbSparse attention ----
        unsigned r0, r1;
        threefry2x32(0u, 42u, 0u, (unsigned)l, r0, r1);
        unsigned k2a, k2b;
        threefry2x32(r0, r1, 0u, 1u, k2a, k2b);
        rng_idx_kernel<<<(NLQ * NU + 255) / 256, 256>>>(k2a, k2b);
        qks_m_kernel<<<(NB * NH * NLQ * 32) / 256, 256>>>();
        topk_kernel<<<NB * NH, 256>>>();
        vmean_kernel<<<NB * NH, 256>>>();
        ctx_init_kernel<<<(NB * NLQ * ND + 255) / 256, 256>>>();
        attn_fused_kernel<<<NB * NH * 9, 320, ATTN_SMEM>>>();

        // ---- output projection + LN1 ----
        GEMM_F32(xhi, xlo, woh + (size_t)l * ND * ND, wol + (size_t)l * ND * ND,
                 bo + l * ND, tmp, ND, ND, 0);
        add_ln_kernel<<<Mrows, 256>>>(h, tmp, g1 + l * ND, b1 + l * ND);

        // ---- FFN + LN2 ----
        GEMM_SPL(hhi, hlo, w1h + (size_t)l * NDFF * ND, w1l + (size_t)l * NDFF * ND,
                 bf1 + l * NDFF, xhi, xlo, NDFF, ND, 1);
        GEMM_F32(xhi, xlo, w2h + (size_t)l * ND * NDFF, w2l + (size_t)l * ND * NDFF,
                 bf2 + l * ND, tmp, ND, NDFF, 0);
        add_ln_kernel<<<Mrows, 256>>>(h, tmp, g2 + l * ND, b2 + l * ND);
    }

    final_kernel<<<NB, 256>>>(Wf, bf, (float*)d_out);
#undef GEMM_F32
#undef GEMM_SPL
}